// round 14
// baseline (speedup 1.0000x reference)
#include <cuda_runtime.h>
#include <cstdint>
#include <cstddef>

// Problem constants
#define B_    2
#define S_    2048
#define D_    1024
#define H_    16
#define DK_   64
#define MTOT  4096        // B_*S_
#define HB_   32          // H_*B_

// ---------------------------------------------------------------------------
// Scratch (static device allocations; no dynamic alloc allowed)
// g_qx / g_kx store the dk axis PERMUTED: dk' = (dk&56)|((dk&3)<<1)|((dk>>2)&1)
// (scores invariant; enables paired LDS.64 B-fragment loads in attn).
// g_vx is natural layout (PV + colsum need it).
// ---------------------------------------------------------------------------
static __device__ float g_qx[B_ * H_ * S_ * DK_];   // [b][h][s][dk']
static __device__ float g_kx[B_ * H_ * S_ * DK_];   // [b][h][s][dk']
static __device__ float g_vx[B_ * H_ * S_ * DK_];   // [b][h][s][dk]
static __device__ float g_ctx[(size_t)MTOT * D_];   // [b*S+s][h*64+dk]
static __device__ float g_dense[(size_t)MTOT * D_];
static __device__ float g_rinv[HB_ * S_];           // 1/rowsum per attn row
static __device__ float g_vcs[HB_ * DK_];           // colsum of V per (b*H+h, d)

// ---------------------------------------------------------------------------
// Helpers
// ---------------------------------------------------------------------------
__device__ __forceinline__ float tf32_hi(float x) {
    uint32_t r;
    asm("cvt.rna.tf32.f32 %0, %1;" : "=r"(r) : "f"(x));
    return __uint_as_float(r);
}

__device__ __forceinline__ void mma_tf32(float c[4],
                                         uint32_t a0, uint32_t a1, uint32_t a2, uint32_t a3,
                                         uint32_t b0, uint32_t b1) {
    asm volatile(
        "mma.sync.aligned.m16n8k8.row.col.f32.tf32.tf32.f32 "
        "{%0,%1,%2,%3}, {%4,%5,%6,%7}, {%8,%9}, {%0,%1,%2,%3};\n"
        : "+f"(c[0]), "+f"(c[1]), "+f"(c[2]), "+f"(c[3])
        : "r"(a0), "r"(a1), "r"(a2), "r"(a3), "r"(b0), "r"(b1));
}

__device__ __forceinline__ void cp_async16(uint32_t smem_addr, const void* gptr) {
    asm volatile("cp.async.cg.shared.global [%0], [%1], 16;"
                 :: "r"(smem_addr), "l"(gptr));
}

// ---------------------------------------------------------------------------
// QKV projection GEMM (1xTF32, cp.async double-buffered raw staging).
// mode 0 -> g_qx (permuted dk, also zeroes g_vcs), mode 1 -> g_kx (permuted),
// mode 2 -> g_vx (natural dk, accumulates g_vcs colsums via atomics).
// ---------------------------------------------------------------------------
__global__ __launch_bounds__(256) void qkv_gemm(const float* __restrict__ A,
                                                const float* __restrict__ W,
                                                const float* __restrict__ bias,
                                                int mode) {
    __shared__ float As[2][128 * 20];
    __shared__ float Bs[2][128 * 20];

    const int tid  = threadIdx.x;
    const int lane = tid & 31;
    const int warp = tid >> 5;
    const int wm   = warp & 1;
    const int wn   = warp >> 1;
    const int m0   = blockIdx.x * 128;
    const int n0   = blockIdx.y * 128;

    if (mode == 0 && blockIdx.x == 0 && blockIdx.y == 0) {
#pragma unroll
        for (int i = 0; i < 8; i++) g_vcs[tid + i * 256] = 0.f;
    }

    const int r0 = tid >> 2;
    const int c0 = (tid & 3) * 4;

    float c[4][4][4];
#pragma unroll
    for (int i = 0; i < 4; i++)
#pragma unroll
        for (int j = 0; j < 4; j++)
#pragma unroll
            for (int k = 0; k < 4; k++) c[i][j][k] = 0.f;

    {
        uint32_t as = (uint32_t)__cvta_generic_to_shared(&As[0][0]);
        uint32_t bs = (uint32_t)__cvta_generic_to_shared(&Bs[0][0]);
#pragma unroll
        for (int i = 0; i < 2; i++) {
            int r = r0 + i * 64;
            cp_async16(as + (r * 20 + c0) * 4, A + (size_t)(m0 + r) * 1024 + c0);
            cp_async16(bs + (r * 20 + c0) * 4, W + (size_t)(n0 + r) * 1024 + c0);
        }
        asm volatile("cp.async.commit_group;");
    }

    for (int kt = 0; kt < 64; kt++) {
        asm volatile("cp.async.wait_group 0;");
        __syncthreads();

        if (kt + 1 < 64) {
            int buf = (kt + 1) & 1;
            int k0  = (kt + 1) * 16;
            uint32_t as = (uint32_t)__cvta_generic_to_shared(&As[buf][0]);
            uint32_t bs = (uint32_t)__cvta_generic_to_shared(&Bs[buf][0]);
#pragma unroll
            for (int i = 0; i < 2; i++) {
                int r = r0 + i * 64;
                cp_async16(as + (r * 20 + c0) * 4, A + (size_t)(m0 + r) * 1024 + k0 + c0);
                cp_async16(bs + (r * 20 + c0) * 4, W + (size_t)(n0 + r) * 1024 + k0 + c0);
            }
            asm volatile("cp.async.commit_group;");
        }

        const float* Ab = As[kt & 1];
        const float* Bb = Bs[kt & 1];
#pragma unroll
        for (int kg = 0; kg < 16; kg += 8) {
            uint32_t bh[4][2];
#pragma unroll
            for (int nt = 0; nt < 4; nt++) {
                int boff = (wn * 32 + nt * 8 + (lane >> 2)) * 20 + kg + (lane & 3);
                bh[nt][0] = __float_as_uint(Bb[boff]);
                bh[nt][1] = __float_as_uint(Bb[boff + 4]);
            }
#pragma unroll
            for (int mt = 0; mt < 4; mt++) {
                int aoff = (wm * 64 + mt * 16 + (lane >> 2)) * 20 + kg + (lane & 3);
                uint32_t a0 = __float_as_uint(Ab[aoff]);
                uint32_t a1 = __float_as_uint(Ab[aoff + 8 * 20]);
                uint32_t a2 = __float_as_uint(Ab[aoff + 4]);
                uint32_t a3 = __float_as_uint(Ab[aoff + 8 * 20 + 4]);
#pragma unroll
                for (int nt = 0; nt < 4; nt++)
                    mma_tf32(c[mt][nt], a0, a1, a2, a3, bh[nt][0], bh[nt][1]);
            }
        }
    }

    __syncthreads();

    float csum[4][2];
#pragma unroll
    for (int nt = 0; nt < 4; nt++) { csum[nt][0] = 0.f; csum[nt][1] = 0.f; }

#pragma unroll
    for (int mt = 0; mt < 4; mt++) {
#pragma unroll
        for (int nt = 0; nt < 4; nt++) {
#pragma unroll
            for (int j = 0; j < 4; j++) {
                int row = m0 + wm * 64 + mt * 16 + (lane >> 2) + ((j >> 1) << 3);
                int col = n0 + wn * 32 + nt * 8 + 2 * (lane & 3) + (j & 1);
                float v = c[mt][nt][j] + bias[col];
                int b  = row >> 11;
                int s  = row & 2047;
                int h  = col >> 6;
                int dk = col & 63;
                if (mode == 2) {
                    csum[nt][j & 1] += v;
                    g_vx[(((size_t)(b * H_ + h)) * S_ + s) * DK_ + dk] = v;
                } else {
                    int dkp = (dk & 56) | ((dk & 3) << 1) | ((dk >> 2) & 1);
                    float* dst = (mode == 0) ? g_qx : g_kx;
                    dst[(((size_t)(b * H_ + h)) * S_ + s) * DK_ + dkp] = v;
                }
            }
        }
    }

    if (mode == 2) {
#pragma unroll
        for (int nt = 0; nt < 4; nt++) {
#pragma unroll
            for (int p = 0; p < 2; p++) {
                float v = csum[nt][p];
                v += __shfl_down_sync(0xffffffffu, v, 16);
                v += __shfl_down_sync(0xffffffffu, v, 8);
                v += __shfl_down_sync(0xffffffffu, v, 4);
                if (lane < 4) {
                    int col = n0 + wn * 32 + nt * 8 + 2 * lane + p;
                    int b   = m0 >> 11;
                    int bh  = b * H_ + (col >> 6);
                    atomicAdd(&g_vcs[bh * 64 + (col & 63)], v);
                }
            }
        }
    }
}

// ---------------------------------------------------------------------------
// Dense GEMM (3xTF32 RN via register hi/lo split; cp.async raw staging):
// g_dense = relu(g_ctx @ dense_w^T + dense_b)
// ---------------------------------------------------------------------------
__global__ __launch_bounds__(256) void dense_gemm(const float* __restrict__ W,
                                                  const float* __restrict__ bias) {
    __shared__ float As[2][128 * 20];
    __shared__ float Bs[2][128 * 20];

    const float* Ap = g_ctx;

    const int tid  = threadIdx.x;
    const int lane = tid & 31;
    const int warp = tid >> 5;
    const int wm   = warp & 1;
    const int wn   = warp >> 1;
    const int m0   = blockIdx.x * 128;
    const int n0   = blockIdx.y * 128;

    const int r0 = tid >> 2;
    const int c0 = (tid & 3) * 4;

    float c[4][4][4];
#pragma unroll
    for (int i = 0; i < 4; i++)
#pragma unroll
        for (int j = 0; j < 4; j++)
#pragma unroll
            for (int k = 0; k < 4; k++) c[i][j][k] = 0.f;

    {
        uint32_t as = (uint32_t)__cvta_generic_to_shared(&As[0][0]);
        uint32_t bs = (uint32_t)__cvta_generic_to_shared(&Bs[0][0]);
#pragma unroll
        for (int i = 0; i < 2; i++) {
            int r = r0 + i * 64;
            cp_async16(as + (r * 20 + c0) * 4, Ap + (size_t)(m0 + r) * 1024 + c0);
            cp_async16(bs + (r * 20 + c0) * 4, W + (size_t)(n0 + r) * 1024 + c0);
        }
        asm volatile("cp.async.commit_group;");
    }

    for (int kt = 0; kt < 64; kt++) {
        asm volatile("cp.async.wait_group 0;");
        __syncthreads();

        if (kt + 1 < 64) {
            int buf = (kt + 1) & 1;
            int k0  = (kt + 1) * 16;
            uint32_t as = (uint32_t)__cvta_generic_to_shared(&As[buf][0]);
            uint32_t bs = (uint32_t)__cvta_generic_to_shared(&Bs[buf][0]);
#pragma unroll
            for (int i = 0; i < 2; i++) {
                int r = r0 + i * 64;
                cp_async16(as + (r * 20 + c0) * 4, Ap + (size_t)(m0 + r) * 1024 + k0 + c0);
                cp_async16(bs + (r * 20 + c0) * 4, W + (size_t)(n0 + r) * 1024 + k0 + c0);
            }
            asm volatile("cp.async.commit_group;");
        }

        const float* Ab = As[kt & 1];
        const float* Bb = Bs[kt & 1];
#pragma unroll
        for (int kg = 0; kg < 16; kg += 8) {
            uint32_t bh[4][2], bl[4][2];
#pragma unroll
            for (int nt = 0; nt < 4; nt++) {
                int boff = (wn * 32 + nt * 8 + (lane >> 2)) * 20 + kg + (lane & 3);
                float rb0 = Bb[boff];
                float rb1 = Bb[boff + 4];
                float hb0 = tf32_hi(rb0);
                float hb1 = tf32_hi(rb1);
                bh[nt][0] = __float_as_uint(hb0);
                bh[nt][1] = __float_as_uint(hb1);
                bl[nt][0] = __float_as_uint(rb0 - hb0);
                bl[nt][1] = __float_as_uint(rb1 - hb1);
            }
#pragma unroll
            for (int mt = 0; mt < 4; mt++) {
                int aoff = (wm * 64 + mt * 16 + (lane >> 2)) * 20 + kg + (lane & 3);
                float ra0 = Ab[aoff];
                float ra1 = Ab[aoff + 8 * 20];
                float ra2 = Ab[aoff + 4];
                float ra3 = Ab[aoff + 8 * 20 + 4];
                float ha0 = tf32_hi(ra0), ha1 = tf32_hi(ra1);
                float ha2 = tf32_hi(ra2), ha3 = tf32_hi(ra3);
                uint32_t ah0 = __float_as_uint(ha0), ah1 = __float_as_uint(ha1);
                uint32_t ah2 = __float_as_uint(ha2), ah3 = __float_as_uint(ha3);
                uint32_t al0 = __float_as_uint(ra0 - ha0), al1 = __float_as_uint(ra1 - ha1);
                uint32_t al2 = __float_as_uint(ra2 - ha2), al3 = __float_as_uint(ra3 - ha3);
#pragma unroll
                for (int nt = 0; nt < 4; nt++) {
                    mma_tf32(c[mt][nt], ah0, ah1, ah2, ah3, bh[nt][0], bh[nt][1]);
                    mma_tf32(c[mt][nt], ah0, ah1, ah2, ah3, bl[nt][0], bl[nt][1]);
                    mma_tf32(c[mt][nt], al0, al1, al2, al3, bh[nt][0], bh[nt][1]);
                }
            }
        }
    }

    __syncthreads();
#pragma unroll
    for (int mt = 0; mt < 4; mt++) {
#pragma unroll
        for (int nt = 0; nt < 4; nt++) {
#pragma unroll
            for (int j = 0; j < 4; j++) {
                int row = m0 + wm * 64 + mt * 16 + (lane >> 2) + ((j >> 1) << 3);
                int col = n0 + wn * 32 + nt * 8 + 2 * (lane & 3) + (j & 1);
                float v = c[mt][nt][j] + bias[col];
                g_dense[(size_t)row * 1024 + col] = v > 0.f ? v : 0.f;
            }
        }
    }
}

// ---------------------------------------------------------------------------
// Fused attention kernel (v6: 32 q-rows/warp, 128 q-rows/block -> K/V L1
// bytes per unit work halved; PV transposed with shuffle-fed dp as v5).
// grid = (S/128, H*B), block = 256 (8 warps: wm 0..3 = 32 q-rows, wn 0..1 =
// kv half). 1 CTA/SM (register-heavy by design; kernel is L1-BW-bound).
// ---------------------------------------------------------------------------
#define KSTR 72
#define VSTR 72
#define KVBUF (64 * KSTR + 64 * VSTR)   // 9216 floats per buffer
#define OSTR 66
#define ATTN_SMEM_FLOATS (2 * KVBUF + 128)   // 18560 floats = 74240 B

__global__ __launch_bounds__(256, 1) void attn_kernel(float* __restrict__ attn_out) {
    extern __shared__ float smf[];
    float* rs   = smf + 2 * KVBUF;           // rowsum[128]
    float* Obuf = smf;                       // epilogue alias: 2 x 128 x 66 (16896 <= 18432)

    const int tid  = threadIdx.x;
    const int lane = tid & 31;
    const int warp = tid >> 5;
    const int wm   = warp & 3;               // q-row group (32 rows each)
    const int wn   = warp >> 2;              // kv half
    const int g    = lane >> 2;
    const int j    = lane & 3;
    const int hb   = blockIdx.y;             // h*B + b
    const int h    = hb >> 1;
    const int b    = hb & 1;
    const int q0   = blockIdx.x * 128;

    const float* qbase = g_qx + ((size_t)(b * H_ + h)) * S_ * DK_;
    const float* kbase = g_kx + ((size_t)(b * H_ + h)) * S_ * DK_;
    const float* vbase = g_vx + ((size_t)(b * H_ + h)) * S_ * DK_;
    const float invT = 0.03125f;             // 1/sqrt(1024)

    if (tid < 128) rs[tid] = 0.f;

    const int sr  = tid >> 4;                // base row 0..15 (+16 per i)
    const int sc4 = (tid & 15) * 4;          // col 0..60

    // prologue: issue tile 0 loads
    {
        float* Kb = smf;
        float* Vb = smf + 64 * KSTR;
        uint32_t ksm = (uint32_t)__cvta_generic_to_shared(Kb);
        uint32_t vsm = (uint32_t)__cvta_generic_to_shared(Vb);
#pragma unroll
        for (int i = 0; i < 4; i++) {
            int r = sr + i * 16;
            cp_async16(ksm + (r * KSTR + sc4) * 4, kbase + (size_t)r * 64 + sc4);
            cp_async16(vsm + (r * VSTR + sc4) * 4, vbase + (size_t)r * 64 + sc4);
        }
        asm volatile("cp.async.commit_group;");
    }

    // Q fragments in registers (RN tf32, pre-scaled), permuted layout;
    // two 16-row m-tiles per warp (mq = 0, 1).
    uint32_t qa[2][8][4];
#pragma unroll
    for (int mq = 0; mq < 2; mq++) {
        const float* qr0 = qbase + (size_t)(q0 + wm * 32 + mq * 16 + g) * 64;
        const float* qr1 = qr0 + 8 * 64;
#pragma unroll
        for (int kg = 0; kg < 8; kg++) {
            float2 u0 = *(const float2*)(qr0 + kg * 8 + 2 * j);
            float2 u1 = *(const float2*)(qr1 + kg * 8 + 2 * j);
            qa[mq][kg][0] = __float_as_uint(tf32_hi(u0.x * invT));
            qa[mq][kg][2] = __float_as_uint(tf32_hi(u0.y * invT));
            qa[mq][kg][1] = __float_as_uint(tf32_hi(u1.x * invT));
            qa[mq][kg][3] = __float_as_uint(tf32_hi(u1.y * invT));
        }
    }

    // O' accumulators: o[mt][mq][nq][c] -> O'[n = mt*16+g(+8)][q tile mq*16+nq*8]
    float o[4][2][2][4];
#pragma unroll
    for (int mt = 0; mt < 4; mt++)
#pragma unroll
        for (int mq = 0; mq < 2; mq++)
#pragma unroll
            for (int nq = 0; nq < 2; nq++)
#pragma unroll
                for (int k = 0; k < 4; k++) o[mt][mq][nq][k] = 0.f;
    float rsv[2][2] = {{0.f, 0.f}, {0.f, 0.f}};

    const int src0 = 4 * g + (j >> 1);       // shuffle source lanes
    const int src1 = src0 + 2;
    const bool jodd = (j & 1) != 0;

    for (int kt = 0; kt < 32; kt++) {
        float* Kb = smf + (kt & 1) * KVBUF;
        float* Vb = Kb + 64 * KSTR;

        asm volatile("cp.async.wait_group 0;");
        __syncthreads();

        if (kt + 1 < 32) {
            float* Kn = smf + ((kt + 1) & 1) * KVBUF;
            float* Vn = Kn + 64 * KSTR;
            uint32_t ksm = (uint32_t)__cvta_generic_to_shared(Kn);
            uint32_t vsm = (uint32_t)__cvta_generic_to_shared(Vn);
            const float* kb = kbase + (size_t)(kt + 1) * 64 * 64;
            const float* vb = vbase + (size_t)(kt + 1) * 64 * 64;
#pragma unroll
            for (int i = 0; i < 4; i++) {
                int r = sr + i * 16;
                cp_async16(ksm + (r * KSTR + sc4) * 4, kb + (size_t)r * 64 + sc4);
                cp_async16(vsm + (r * VSTR + sc4) * 4, vb + (size_t)r * 64 + sc4);
            }
            asm volatile("cp.async.commit_group;");
        }

        // scores: K B-frags loaded once per kg, reused by both mq tiles
        float s[2][4][4];
#pragma unroll
        for (int mq = 0; mq < 2; mq++)
#pragma unroll
            for (int i = 0; i < 4; i++)
#pragma unroll
                for (int k = 0; k < 4; k++) s[mq][i][k] = 0.f;
#pragma unroll
        for (int kg = 0; kg < 8; kg++) {
            float2 kb2[4];
#pragma unroll
            for (int nt = 0; nt < 4; nt++)
                kb2[nt] = *(const float2*)(Kb + (wn * 32 + nt * 8 + g) * KSTR + kg * 8 + 2 * j);
#pragma unroll
            for (int mq = 0; mq < 2; mq++)
#pragma unroll
                for (int nt = 0; nt < 4; nt++)
                    mma_tf32(s[mq][nt], qa[mq][kg][0], qa[mq][kg][1],
                             qa[mq][kg][2], qa[mq][kg][3],
                             __float_as_uint(kb2[nt].x), __float_as_uint(kb2[nt].y));
        }

        // exp -> gmem attn (unnormalized), rowsum regs; dp overwrites s[][][]
        const int k0 = kt * 64;
#pragma unroll
        for (int mq = 0; mq < 2; mq++) {
            float* ab = attn_out +
                ((size_t)hb * S_ + q0 + wm * 32 + mq * 16 + g) * S_ + k0 + wn * 32;
#pragma unroll
            for (int nt = 0; nt < 4; nt++) {
                float p0 = __expf(s[mq][nt][0]);
                float p1 = __expf(s[mq][nt][1]);
                float p2 = __expf(s[mq][nt][2]);
                float p3 = __expf(s[mq][nt][3]);
                rsv[mq][0] += p0 + p1;
                rsv[mq][1] += p2 + p3;
                *(float2*)(ab + nt * 8 + 2 * j) = make_float2(p0, p1);
                *(float2*)(ab + (size_t)8 * S_ + nt * 8 + 2 * j) = make_float2(p2, p3);
                s[mq][nt][0] = p0 - 1.f;
                s[mq][nt][1] = p1 - 1.f;
                s[mq][nt][2] = p2 - 1.f;
                s[mq][nt][3] = p3 - 1.f;
            }
        }

        // PV (transposed): O'[n][q] += V'[n][k] * dp'[k][q]
        // A-frags = V columns (loaded once per kp, reused by all 4 q-subtiles)
#pragma unroll
        for (int kp = 0; kp < 4; kp++) {
            uint32_t av[4][4];
#pragma unroll
            for (int mt = 0; mt < 4; mt++) {
                int aoff = (wn * 32 + kp * 8 + j) * VSTR + mt * 16 + g;
                av[mt][0] = __float_as_uint(Vb[aoff]);
                av[mt][1] = __float_as_uint(Vb[aoff + 8]);
                av[mt][2] = __float_as_uint(Vb[aoff + 4 * VSTR]);
                av[mt][3] = __float_as_uint(Vb[aoff + 4 * VSTR + 8]);
            }
#pragma unroll
            for (int mq = 0; mq < 2; mq++) {
#pragma unroll
                for (int nq = 0; nq < 2; nq++) {
                    float v00 = __shfl_sync(0xffffffffu, s[mq][kp][2 * nq + 0], src0);
                    float v01 = __shfl_sync(0xffffffffu, s[mq][kp][2 * nq + 1], src0);
                    float v10 = __shfl_sync(0xffffffffu, s[mq][kp][2 * nq + 0], src1);
                    float v11 = __shfl_sync(0xffffffffu, s[mq][kp][2 * nq + 1], src1);
                    uint32_t b0 = __float_as_uint(jodd ? v01 : v00);
                    uint32_t b1 = __float_as_uint(jodd ? v11 : v10);
#pragma unroll
                    for (int mt = 0; mt < 4; mt++)
                        mma_tf32(o[mt][mq][nq], av[mt][0], av[mt][1], av[mt][2], av[mt][3],
                                 b0, b1);
                }
            }
        }
    }

    // --- epilogue ---
    __syncthreads();   // all PV reads of the KV buffers complete before aliasing
    {
        float* Ob = Obuf + wn * 128 * OSTR;
#pragma unroll
        for (int mt = 0; mt < 4; mt++) {
#pragma unroll
            for (int mq = 0; mq < 2; mq++) {
#pragma unroll
                for (int nq = 0; nq < 2; nq++) {
                    int qb = wm * 32 + mq * 16 + nq * 8 + 2 * j;
                    int nb = mt * 16 + g;
                    Ob[qb * OSTR + nb]           = o[mt][mq][nq][0];
                    Ob[(qb + 1) * OSTR + nb]     = o[mt][mq][nq][1];
                    Ob[qb * OSTR + nb + 8]       = o[mt][mq][nq][2];
                    Ob[(qb + 1) * OSTR + nb + 8] = o[mt][mq][nq][3];
                }
            }
        }
    }
#pragma unroll
    for (int mq = 0; mq < 2; mq++) {
        float r0 = rsv[mq][0], r1 = rsv[mq][1];
        r0 += __shfl_xor_sync(0xffffffffu, r0, 1);
        r0 += __shfl_xor_sync(0xffffffffu, r0, 2);
        r1 += __shfl_xor_sync(0xffffffffu, r1, 1);
        r1 += __shfl_xor_sync(0xffffffffu, r1, 2);
        if (j == 0) {
            atomicAdd(&rs[wm * 32 + mq * 16 + g], r0);
            atomicAdd(&rs[wm * 32 + mq * 16 + 8 + g], r1);
        }
    }
    __syncthreads();
    if (tid < 128) {
        float inv = 1.0f / rs[tid];
        g_rinv[(size_t)hb * S_ + q0 + tid] = inv;
        rs[tid] = inv;
    }
    __syncthreads();

    const float* vc = g_vcs + (b * H_ + h) * 64;
#pragma unroll
    for (int i = 0; i < 32; i++) {
        int lin = tid + i * 256;
        int qr  = lin >> 6;
        int d   = lin & 63;
        float val = (Obuf[qr * OSTR + d] + Obuf[128 * OSTR + qr * OSTR + d] + vc[d]) * rs[qr];
        g_ctx[((size_t)(b * S_ + q0 + qr)) * D_ + h * 64 + d] = val;
    }
}

// ---------------------------------------------------------------------------
// Normalize attn in place: attn[hb][q][k] *= g_rinv[hb*S+q]
// ---------------------------------------------------------------------------
__global__ __launch_bounds__(256) void attn_norm(float* __restrict__ attn) {
    size_t i = (size_t)blockIdx.x * 256 + threadIdx.x;  // float4 index
    float inv = g_rinv[i >> 9];                          // 512 float4 per row
    float4* p = (float4*)attn;
    float4 v = p[i];
    v.x *= inv; v.y *= inv; v.z *= inv; v.w *= inv;
    p[i] = v;
}

// ---------------------------------------------------------------------------
// LayerNorm over rows of g_dense -> out
// ---------------------------------------------------------------------------
__global__ __launch_bounds__(256) void ln_kernel(const float* __restrict__ lg,
                                                 const float* __restrict__ lb,
                                                 float* __restrict__ out) {
    const int row = blockIdx.x;
    const int tid = threadIdx.x;
    const float* x = g_dense + (size_t)row * 1024;
    float4 xv = *(const float4*)(x + tid * 4);
    float s  = xv.x + xv.y + xv.z + xv.w;
    float ss = fmaf(xv.x, xv.x, fmaf(xv.y, xv.y, fmaf(xv.z, xv.z, xv.w * xv.w)));
#pragma unroll
    for (int off = 16; off > 0; off >>= 1) {
        s  += __shfl_xor_sync(0xffffffffu, s, off);
        ss += __shfl_xor_sync(0xffffffffu, ss, off);
    }
    __shared__ float sm1[8], sm2[8];
    if ((tid & 31) == 0) { sm1[tid >> 5] = s; sm2[tid >> 5] = ss; }
    __syncthreads();
    if (tid < 32) {
        float a  = (tid < 8) ? sm1[tid] : 0.f;
        float b2 = (tid < 8) ? sm2[tid] : 0.f;
#pragma unroll
        for (int off = 4; off > 0; off >>= 1) {
            a  += __shfl_xor_sync(0xffffffffu, a, off);
            b2 += __shfl_xor_sync(0xffffffffu, b2, off);
        }
        if (tid == 0) { sm1[0] = a; sm2[0] = b2; }
    }
    __syncthreads();
    float mean = sm1[0] * (1.0f / 1024.0f);
    float var  = sm2[0] * (1.0f / 1024.0f) - mean * mean;
    float rstd = rsqrtf(var + 1e-5f);
    float4 gv = *(const float4*)(lg + tid * 4);
    float4 bv = *(const float4*)(lb + tid * 4);
    float4 ov;
    ov.x = (xv.x - mean) * rstd * gv.x + bv.x;
    ov.y = (xv.y - mean) * rstd * gv.y + bv.y;
    ov.z = (xv.z - mean) * rstd * gv.z + bv.z;
    ov.w = (xv.w - mean) * rstd * gv.w + bv.w;
    *(float4*)(out + (size_t)row * 1024 + tid * 4) = ov;
}

// ---------------------------------------------------------------------------
// Launch (7 launches; attn is #4 so the harness ncu capture samples it)
// ---------------------------------------------------------------------------
extern "C" void kernel_launch(void* const* d_in, const int* in_sizes, int n_in,
                              void* d_out, int out_size) {
    const float* k_in = (const float*)d_in[0];
    const float* q_in = (const float*)d_in[1];
    const float* wk   = (const float*)d_in[2];
    const float* bk   = (const float*)d_in[3];
    const float* wq   = (const float*)d_in[4];
    const float* bq   = (const float*)d_in[5];
    const float* wv   = (const float*)d_in[6];
    const float* bv   = (const float*)d_in[7];
    const float* wd   = (const float*)d_in[8];
    const float* bd   = (const float*)d_in[9];
    const float* lg   = (const float*)d_in[10];
    const float* lb   = (const float*)d_in[11];

    float* out  = (float*)d_out;
    float* attn = out + (size_t)B_ * S_ * D_;  // tuple order: (out, attn)

    const int attn_smem_bytes = ATTN_SMEM_FLOATS * 4;  // 74240 B
    cudaFuncSetAttribute(attn_kernel, cudaFuncAttributeMaxDynamicSharedMemorySize,
                         attn_smem_bytes);

    dim3 pgrid(MTOT / 128, D_ / 128);  // (32, 8)
    qkv_gemm<<<pgrid, 256>>>(q_in, wq, bq, 0);   // g_qx (permuted) + zero g_vcs
    qkv_gemm<<<pgrid, 256>>>(k_in, wk, bk, 1);   // g_kx (permuted)
    qkv_gemm<<<pgrid, 256>>>(k_in, wv, bv, 2);   // g_vx + colsums (v = k)

    attn_kernel<<<dim3(S_ / 128, HB_), 256, attn_smem_bytes>>>(attn);

    attn_norm<<<131072, 256>>>(attn);

    dense_gemm<<<pgrid, 256>>>(wd, bd);          // dense + relu -> g_dense
    ln_kernel<<<MTOT, 256>>>(lg, lb, out);
}

// round 15
// speedup vs baseline: 1.0020x; 1.0020x over previous
#include <cuda_runtime.h>
#include <cstdint>
#include <cstddef>

// Problem constants
#define B_    2
#define S_    2048
#define D_    1024
#define H_    16
#define DK_   64
#define MTOT  4096        // B_*S_
#define HB_   32          // H_*B_

// ---------------------------------------------------------------------------
// Scratch (static device allocations; no dynamic alloc allowed)
// g_qx / g_kx store the dk axis PERMUTED: dk' = (dk&56)|((dk&3)<<1)|((dk>>2)&1)
// (scores invariant; enables paired LDS.64 B-fragment loads in attn).
// g_vx is natural layout (PV + colsum need it).
// ---------------------------------------------------------------------------
static __device__ float g_qx[B_ * H_ * S_ * DK_];   // [b][h][s][dk']
static __device__ float g_kx[B_ * H_ * S_ * DK_];   // [b][h][s][dk']
static __device__ float g_vx[B_ * H_ * S_ * DK_];   // [b][h][s][dk]
static __device__ float g_ctx[(size_t)MTOT * D_];   // [b*S+s][h*64+dk]
static __device__ float g_dense[(size_t)MTOT * D_];
static __device__ float g_rinv[HB_ * S_];           // 1/rowsum per attn row
static __device__ float g_vcs[HB_ * DK_];           // colsum of V per (b*H+h, d)

// ---------------------------------------------------------------------------
// Helpers
// ---------------------------------------------------------------------------
__device__ __forceinline__ float tf32_hi(float x) {
    uint32_t r;
    asm("cvt.rna.tf32.f32 %0, %1;" : "=r"(r) : "f"(x));
    return __uint_as_float(r);
}

__device__ __forceinline__ void mma_tf32(float c[4],
                                         uint32_t a0, uint32_t a1, uint32_t a2, uint32_t a3,
                                         uint32_t b0, uint32_t b1) {
    asm volatile(
        "mma.sync.aligned.m16n8k8.row.col.f32.tf32.tf32.f32 "
        "{%0,%1,%2,%3}, {%4,%5,%6,%7}, {%8,%9}, {%0,%1,%2,%3};\n"
        : "+f"(c[0]), "+f"(c[1]), "+f"(c[2]), "+f"(c[3])
        : "r"(a0), "r"(a1), "r"(a2), "r"(a3), "r"(b0), "r"(b1));
}

__device__ __forceinline__ void cp_async16(uint32_t smem_addr, const void* gptr) {
    asm volatile("cp.async.cg.shared.global [%0], [%1], 16;"
                 :: "r"(smem_addr), "l"(gptr));
}

// ---------------------------------------------------------------------------
// QKV projection GEMM (1xTF32, cp.async double-buffered raw staging).
// mode 0 -> g_qx (permuted dk, also zeroes g_vcs), mode 1 -> g_kx (permuted),
// mode 2 -> g_vx (natural dk, accumulates g_vcs colsums via atomics).
// ---------------------------------------------------------------------------
__global__ __launch_bounds__(256) void qkv_gemm(const float* __restrict__ A,
                                                const float* __restrict__ W,
                                                const float* __restrict__ bias,
                                                int mode) {
    __shared__ float As[2][128 * 20];
    __shared__ float Bs[2][128 * 20];

    const int tid  = threadIdx.x;
    const int lane = tid & 31;
    const int warp = tid >> 5;
    const int wm   = warp & 1;
    const int wn   = warp >> 1;
    const int m0   = blockIdx.x * 128;
    const int n0   = blockIdx.y * 128;

    if (mode == 0 && blockIdx.x == 0 && blockIdx.y == 0) {
#pragma unroll
        for (int i = 0; i < 8; i++) g_vcs[tid + i * 256] = 0.f;
    }

    const int r0 = tid >> 2;
    const int c0 = (tid & 3) * 4;

    float c[4][4][4];
#pragma unroll
    for (int i = 0; i < 4; i++)
#pragma unroll
        for (int j = 0; j < 4; j++)
#pragma unroll
            for (int k = 0; k < 4; k++) c[i][j][k] = 0.f;

    {
        uint32_t as = (uint32_t)__cvta_generic_to_shared(&As[0][0]);
        uint32_t bs = (uint32_t)__cvta_generic_to_shared(&Bs[0][0]);
#pragma unroll
        for (int i = 0; i < 2; i++) {
            int r = r0 + i * 64;
            cp_async16(as + (r * 20 + c0) * 4, A + (size_t)(m0 + r) * 1024 + c0);
            cp_async16(bs + (r * 20 + c0) * 4, W + (size_t)(n0 + r) * 1024 + c0);
        }
        asm volatile("cp.async.commit_group;");
    }

    for (int kt = 0; kt < 64; kt++) {
        asm volatile("cp.async.wait_group 0;");
        __syncthreads();

        if (kt + 1 < 64) {
            int buf = (kt + 1) & 1;
            int k0  = (kt + 1) * 16;
            uint32_t as = (uint32_t)__cvta_generic_to_shared(&As[buf][0]);
            uint32_t bs = (uint32_t)__cvta_generic_to_shared(&Bs[buf][0]);
#pragma unroll
            for (int i = 0; i < 2; i++) {
                int r = r0 + i * 64;
                cp_async16(as + (r * 20 + c0) * 4, A + (size_t)(m0 + r) * 1024 + k0 + c0);
                cp_async16(bs + (r * 20 + c0) * 4, W + (size_t)(n0 + r) * 1024 + k0 + c0);
            }
            asm volatile("cp.async.commit_group;");
        }

        const float* Ab = As[kt & 1];
        const float* Bb = Bs[kt & 1];
#pragma unroll
        for (int kg = 0; kg < 16; kg += 8) {
            uint32_t bh[4][2];
#pragma unroll
            for (int nt = 0; nt < 4; nt++) {
                int boff = (wn * 32 + nt * 8 + (lane >> 2)) * 20 + kg + (lane & 3);
                bh[nt][0] = __float_as_uint(Bb[boff]);
                bh[nt][1] = __float_as_uint(Bb[boff + 4]);
            }
#pragma unroll
            for (int mt = 0; mt < 4; mt++) {
                int aoff = (wm * 64 + mt * 16 + (lane >> 2)) * 20 + kg + (lane & 3);
                uint32_t a0 = __float_as_uint(Ab[aoff]);
                uint32_t a1 = __float_as_uint(Ab[aoff + 8 * 20]);
                uint32_t a2 = __float_as_uint(Ab[aoff + 4]);
                uint32_t a3 = __float_as_uint(Ab[aoff + 8 * 20 + 4]);
#pragma unroll
                for (int nt = 0; nt < 4; nt++)
                    mma_tf32(c[mt][nt], a0, a1, a2, a3, bh[nt][0], bh[nt][1]);
            }
        }
    }

    __syncthreads();

    float csum[4][2];
#pragma unroll
    for (int nt = 0; nt < 4; nt++) { csum[nt][0] = 0.f; csum[nt][1] = 0.f; }

#pragma unroll
    for (int mt = 0; mt < 4; mt++) {
#pragma unroll
        for (int nt = 0; nt < 4; nt++) {
#pragma unroll
            for (int j = 0; j < 4; j++) {
                int row = m0 + wm * 64 + mt * 16 + (lane >> 2) + ((j >> 1) << 3);
                int col = n0 + wn * 32 + nt * 8 + 2 * (lane & 3) + (j & 1);
                float v = c[mt][nt][j] + bias[col];
                int b  = row >> 11;
                int s  = row & 2047;
                int h  = col >> 6;
                int dk = col & 63;
                if (mode == 2) {
                    csum[nt][j & 1] += v;
                    g_vx[(((size_t)(b * H_ + h)) * S_ + s) * DK_ + dk] = v;
                } else {
                    int dkp = (dk & 56) | ((dk & 3) << 1) | ((dk >> 2) & 1);
                    float* dst = (mode == 0) ? g_qx : g_kx;
                    dst[(((size_t)(b * H_ + h)) * S_ + s) * DK_ + dkp] = v;
                }
            }
        }
    }

    if (mode == 2) {
#pragma unroll
        for (int nt = 0; nt < 4; nt++) {
#pragma unroll
            for (int p = 0; p < 2; p++) {
                float v = csum[nt][p];
                v += __shfl_down_sync(0xffffffffu, v, 16);
                v += __shfl_down_sync(0xffffffffu, v, 8);
                v += __shfl_down_sync(0xffffffffu, v, 4);
                if (lane < 4) {
                    int col = n0 + wn * 32 + nt * 8 + 2 * lane + p;
                    int b   = m0 >> 11;
                    int bh  = b * H_ + (col >> 6);
                    atomicAdd(&g_vcs[bh * 64 + (col & 63)], v);
                }
            }
        }
    }
}

// ---------------------------------------------------------------------------
// Dense GEMM (3xTF32 RN via register hi/lo split; cp.async raw staging):
// g_dense = relu(g_ctx @ dense_w^T + dense_b)
// ---------------------------------------------------------------------------
__global__ __launch_bounds__(256) void dense_gemm(const float* __restrict__ W,
                                                  const float* __restrict__ bias) {
    __shared__ float As[2][128 * 20];
    __shared__ float Bs[2][128 * 20];

    const float* Ap = g_ctx;

    const int tid  = threadIdx.x;
    const int lane = tid & 31;
    const int warp = tid >> 5;
    const int wm   = warp & 1;
    const int wn   = warp >> 1;
    const int m0   = blockIdx.x * 128;
    const int n0   = blockIdx.y * 128;

    const int r0 = tid >> 2;
    const int c0 = (tid & 3) * 4;

    float c[4][4][4];
#pragma unroll
    for (int i = 0; i < 4; i++)
#pragma unroll
        for (int j = 0; j < 4; j++)
#pragma unroll
            for (int k = 0; k < 4; k++) c[i][j][k] = 0.f;

    {
        uint32_t as = (uint32_t)__cvta_generic_to_shared(&As[0][0]);
        uint32_t bs = (uint32_t)__cvta_generic_to_shared(&Bs[0][0]);
#pragma unroll
        for (int i = 0; i < 2; i++) {
            int r = r0 + i * 64;
            cp_async16(as + (r * 20 + c0) * 4, Ap + (size_t)(m0 + r) * 1024 + c0);
            cp_async16(bs + (r * 20 + c0) * 4, W + (size_t)(n0 + r) * 1024 + c0);
        }
        asm volatile("cp.async.commit_group;");
    }

    for (int kt = 0; kt < 64; kt++) {
        asm volatile("cp.async.wait_group 0;");
        __syncthreads();

        if (kt + 1 < 64) {
            int buf = (kt + 1) & 1;
            int k0  = (kt + 1) * 16;
            uint32_t as = (uint32_t)__cvta_generic_to_shared(&As[buf][0]);
            uint32_t bs = (uint32_t)__cvta_generic_to_shared(&Bs[buf][0]);
#pragma unroll
            for (int i = 0; i < 2; i++) {
                int r = r0 + i * 64;
                cp_async16(as + (r * 20 + c0) * 4, Ap + (size_t)(m0 + r) * 1024 + k0 + c0);
                cp_async16(bs + (r * 20 + c0) * 4, W + (size_t)(n0 + r) * 1024 + k0 + c0);
            }
            asm volatile("cp.async.commit_group;");
        }

        const float* Ab = As[kt & 1];
        const float* Bb = Bs[kt & 1];
#pragma unroll
        for (int kg = 0; kg < 16; kg += 8) {
            uint32_t bh[4][2], bl[4][2];
#pragma unroll
            for (int nt = 0; nt < 4; nt++) {
                int boff = (wn * 32 + nt * 8 + (lane >> 2)) * 20 + kg + (lane & 3);
                float rb0 = Bb[boff];
                float rb1 = Bb[boff + 4];
                float hb0 = tf32_hi(rb0);
                float hb1 = tf32_hi(rb1);
                bh[nt][0] = __float_as_uint(hb0);
                bh[nt][1] = __float_as_uint(hb1);
                bl[nt][0] = __float_as_uint(rb0 - hb0);
                bl[nt][1] = __float_as_uint(rb1 - hb1);
            }
#pragma unroll
            for (int mt = 0; mt < 4; mt++) {
                int aoff = (wm * 64 + mt * 16 + (lane >> 2)) * 20 + kg + (lane & 3);
                float ra0 = Ab[aoff];
                float ra1 = Ab[aoff + 8 * 20];
                float ra2 = Ab[aoff + 4];
                float ra3 = Ab[aoff + 8 * 20 + 4];
                float ha0 = tf32_hi(ra0), ha1 = tf32_hi(ra1);
                float ha2 = tf32_hi(ra2), ha3 = tf32_hi(ra3);
                uint32_t ah0 = __float_as_uint(ha0), ah1 = __float_as_uint(ha1);
                uint32_t ah2 = __float_as_uint(ha2), ah3 = __float_as_uint(ha3);
                uint32_t al0 = __float_as_uint(ra0 - ha0), al1 = __float_as_uint(ra1 - ha1);
                uint32_t al2 = __float_as_uint(ra2 - ha2), al3 = __float_as_uint(ra3 - ha3);
#pragma unroll
                for (int nt = 0; nt < 4; nt++) {
                    mma_tf32(c[mt][nt], ah0, ah1, ah2, ah3, bh[nt][0], bh[nt][1]);
                    mma_tf32(c[mt][nt], ah0, ah1, ah2, ah3, bl[nt][0], bl[nt][1]);
                    mma_tf32(c[mt][nt], al0, al1, al2, al3, bh[nt][0], bh[nt][1]);
                }
            }
        }
    }

    __syncthreads();
#pragma unroll
    for (int mt = 0; mt < 4; mt++) {
#pragma unroll
        for (int nt = 0; nt < 4; nt++) {
#pragma unroll
            for (int j = 0; j < 4; j++) {
                int row = m0 + wm * 64 + mt * 16 + (lane >> 2) + ((j >> 1) << 3);
                int col = n0 + wn * 32 + nt * 8 + 2 * (lane & 3) + (j & 1);
                float v = c[mt][nt][j] + bias[col];
                g_dense[(size_t)row * 1024 + col] = v > 0.f ? v : 0.f;
            }
        }
    }
}

// ---------------------------------------------------------------------------
// Fused attention kernel (v7: v6 tiling + 3-stage cp.async pipeline).
// grid = (S/128, H*B), block = 256 (8 warps: wm 0..3 = 32 q-rows, wn 0..1 =
// kv half). 1 CTA/SM; 3-deep pipeline hides the per-tile load latency that
// v6 exposed (wait_group 1 in steady state).
// ---------------------------------------------------------------------------
#define KSTR 72
#define VSTR 72
#define KVBUF (64 * KSTR + 64 * VSTR)   // 9216 floats per buffer
#define NSTAGE 3
#define OSTR 66
#define ATTN_SMEM_FLOATS (NSTAGE * KVBUF + 128)   // 27776 floats = 111104 B

__global__ __launch_bounds__(256, 1) void attn_kernel(float* __restrict__ attn_out) {
    extern __shared__ float smf[];
    float* rs   = smf + NSTAGE * KVBUF;      // rowsum[128]
    float* Obuf = smf;                       // epilogue alias: 2 x 128 x 66 (16896 <= 27648)

    const int tid  = threadIdx.x;
    const int lane = tid & 31;
    const int warp = tid >> 5;
    const int wm   = warp & 3;               // q-row group (32 rows each)
    const int wn   = warp >> 2;              // kv half
    const int g    = lane >> 2;
    const int j    = lane & 3;
    const int hb   = blockIdx.y;             // h*B + b
    const int h    = hb >> 1;
    const int b    = hb & 1;
    const int q0   = blockIdx.x * 128;

    const float* qbase = g_qx + ((size_t)(b * H_ + h)) * S_ * DK_;
    const float* kbase = g_kx + ((size_t)(b * H_ + h)) * S_ * DK_;
    const float* vbase = g_vx + ((size_t)(b * H_ + h)) * S_ * DK_;
    const float invT = 0.03125f;             // 1/sqrt(1024)

    if (tid < 128) rs[tid] = 0.f;

    const int sr  = tid >> 4;                // base row 0..15 (+16 per i)
    const int sc4 = (tid & 15) * 4;          // col 0..60

    // prologue: issue tiles 0 and 1 (two commit groups)
#pragma unroll
    for (int t = 0; t < 2; t++) {
        float* Kb = smf + t * KVBUF;
        float* Vb = Kb + 64 * KSTR;
        uint32_t ksm = (uint32_t)__cvta_generic_to_shared(Kb);
        uint32_t vsm = (uint32_t)__cvta_generic_to_shared(Vb);
        const float* kb = kbase + (size_t)t * 64 * 64;
        const float* vb = vbase + (size_t)t * 64 * 64;
#pragma unroll
        for (int i = 0; i < 4; i++) {
            int r = sr + i * 16;
            cp_async16(ksm + (r * KSTR + sc4) * 4, kb + (size_t)r * 64 + sc4);
            cp_async16(vsm + (r * VSTR + sc4) * 4, vb + (size_t)r * 64 + sc4);
        }
        asm volatile("cp.async.commit_group;");
    }

    // Q fragments in registers (RN tf32, pre-scaled), permuted layout;
    // two 16-row m-tiles per warp (mq = 0, 1).
    uint32_t qa[2][8][4];
#pragma unroll
    for (int mq = 0; mq < 2; mq++) {
        const float* qr0 = qbase + (size_t)(q0 + wm * 32 + mq * 16 + g) * 64;
        const float* qr1 = qr0 + 8 * 64;
#pragma unroll
        for (int kg = 0; kg < 8; kg++) {
            float2 u0 = *(const float2*)(qr0 + kg * 8 + 2 * j);
            float2 u1 = *(const float2*)(qr1 + kg * 8 + 2 * j);
            qa[mq][kg][0] = __float_as_uint(tf32_hi(u0.x * invT));
            qa[mq][kg][2] = __float_as_uint(tf32_hi(u0.y * invT));
            qa[mq][kg][1] = __float_as_uint(tf32_hi(u1.x * invT));
            qa[mq][kg][3] = __float_as_uint(tf32_hi(u1.y * invT));
        }
    }

    // O' accumulators: o[mt][mq][nq][c] -> O'[n = mt*16+g(+8)][q tile mq*16+nq*8]
    float o[4][2][2][4];
#pragma unroll
    for (int mt = 0; mt < 4; mt++)
#pragma unroll
        for (int mq = 0; mq < 2; mq++)
#pragma unroll
            for (int nq = 0; nq < 2; nq++)
#pragma unroll
                for (int k = 0; k < 4; k++) o[mt][mq][nq][k] = 0.f;
    float rsv[2][2] = {{0.f, 0.f}, {0.f, 0.f}};

    const int src0 = 4 * g + (j >> 1);       // shuffle source lanes
    const int src1 = src0 + 2;
    const bool jodd = (j & 1) != 0;

    int buf = 0;                             // buffer of tile kt (kt % 3)
    for (int kt = 0; kt < 32; kt++) {
        float* Kb = smf + buf * KVBUF;
        float* Vb = Kb + 64 * KSTR;

        // steady state: allow 1 group (tile kt+1) outstanding; tail: drain all
        if (kt < 30) {
            asm volatile("cp.async.wait_group 1;");
        } else {
            asm volatile("cp.async.wait_group 0;");
        }
        __syncthreads();

        if (kt + 2 < 32) {
            int nbuf = buf + 2;
            if (nbuf >= NSTAGE) nbuf -= NSTAGE;
            float* Kn = smf + nbuf * KVBUF;
            float* Vn = Kn + 64 * KSTR;
            uint32_t ksm = (uint32_t)__cvta_generic_to_shared(Kn);
            uint32_t vsm = (uint32_t)__cvta_generic_to_shared(Vn);
            const float* kb = kbase + (size_t)(kt + 2) * 64 * 64;
            const float* vb = vbase + (size_t)(kt + 2) * 64 * 64;
#pragma unroll
            for (int i = 0; i < 4; i++) {
                int r = sr + i * 16;
                cp_async16(ksm + (r * KSTR + sc4) * 4, kb + (size_t)r * 64 + sc4);
                cp_async16(vsm + (r * VSTR + sc4) * 4, vb + (size_t)r * 64 + sc4);
            }
            asm volatile("cp.async.commit_group;");
        }

        // scores: K B-frags loaded once per kg, reused by both mq tiles
        float s[2][4][4];
#pragma unroll
        for (int mq = 0; mq < 2; mq++)
#pragma unroll
            for (int i = 0; i < 4; i++)
#pragma unroll
                for (int k = 0; k < 4; k++) s[mq][i][k] = 0.f;
#pragma unroll
        for (int kg = 0; kg < 8; kg++) {
            float2 kb2[4];
#pragma unroll
            for (int nt = 0; nt < 4; nt++)
                kb2[nt] = *(const float2*)(Kb + (wn * 32 + nt * 8 + g) * KSTR + kg * 8 + 2 * j);
#pragma unroll
            for (int mq = 0; mq < 2; mq++)
#pragma unroll
                for (int nt = 0; nt < 4; nt++)
                    mma_tf32(s[mq][nt], qa[mq][kg][0], qa[mq][kg][1],
                             qa[mq][kg][2], qa[mq][kg][3],
                             __float_as_uint(kb2[nt].x), __float_as_uint(kb2[nt].y));
        }

        // exp -> gmem attn (unnormalized), rowsum regs; dp overwrites s[][][]
        const int k0 = kt * 64;
#pragma unroll
        for (int mq = 0; mq < 2; mq++) {
            float* ab = attn_out +
                ((size_t)hb * S_ + q0 + wm * 32 + mq * 16 + g) * S_ + k0 + wn * 32;
#pragma unroll
            for (int nt = 0; nt < 4; nt++) {
                float p0 = __expf(s[mq][nt][0]);
                float p1 = __expf(s[mq][nt][1]);
                float p2 = __expf(s[mq][nt][2]);
                float p3 = __expf(s[mq][nt][3]);
                rsv[mq][0] += p0 + p1;
                rsv[mq][1] += p2 + p3;
                *(float2*)(ab + nt * 8 + 2 * j) = make_float2(p0, p1);
                *(float2*)(ab + (size_t)8 * S_ + nt * 8 + 2 * j) = make_float2(p2, p3);
                s[mq][nt][0] = p0 - 1.f;
                s[mq][nt][1] = p1 - 1.f;
                s[mq][nt][2] = p2 - 1.f;
                s[mq][nt][3] = p3 - 1.f;
            }
        }

        // PV (transposed): O'[n][q] += V'[n][k] * dp'[k][q]
        // A-frags = V columns (loaded once per kp, reused by all 4 q-subtiles)
#pragma unroll
        for (int kp = 0; kp < 4; kp++) {
            uint32_t av[4][4];
#pragma unroll
            for (int mt = 0; mt < 4; mt++) {
                int aoff = (wn * 32 + kp * 8 + j) * VSTR + mt * 16 + g;
                av[mt][0] = __float_as_uint(Vb[aoff]);
                av[mt][1] = __float_as_uint(Vb[aoff + 8]);
                av[mt][2] = __float_as_uint(Vb[aoff + 4 * VSTR]);
                av[mt][3] = __float_as_uint(Vb[aoff + 4 * VSTR + 8]);
            }
#pragma unroll
            for (int mq = 0; mq < 2; mq++) {
#pragma unroll
                for (int nq = 0; nq < 2; nq++) {
                    float v00 = __shfl_sync(0xffffffffu, s[mq][kp][2 * nq + 0], src0);
                    float v01 = __shfl_sync(0xffffffffu, s[mq][kp][2 * nq + 1], src0);
                    float v10 = __shfl_sync(0xffffffffu, s[mq][kp][2 * nq + 0], src1);
                    float v11 = __shfl_sync(0xffffffffu, s[mq][kp][2 * nq + 1], src1);
                    uint32_t b0 = __float_as_uint(jodd ? v01 : v00);
                    uint32_t b1 = __float_as_uint(jodd ? v11 : v10);
#pragma unroll
                    for (int mt = 0; mt < 4; mt++)
                        mma_tf32(o[mt][mq][nq], av[mt][0], av[mt][1], av[mt][2], av[mt][3],
                                 b0, b1);
                }
            }
        }

        buf++;
        if (buf == NSTAGE) buf = 0;
    }

    // --- epilogue ---
    __syncthreads();   // all PV reads of the KV buffers complete before aliasing
    {
        float* Ob = Obuf + wn * 128 * OSTR;
#pragma unroll
        for (int mt = 0; mt < 4; mt++) {
#pragma unroll
            for (int mq = 0; mq < 2; mq++) {
#pragma unroll
                for (int nq = 0; nq < 2; nq++) {
                    int qb = wm * 32 + mq * 16 + nq * 8 + 2 * j;
                    int nb = mt * 16 + g;
                    Ob[qb * OSTR + nb]           = o[mt][mq][nq][0];
                    Ob[(qb + 1) * OSTR + nb]     = o[mt][mq][nq][1];
                    Ob[qb * OSTR + nb + 8]       = o[mt][mq][nq][2];
                    Ob[(qb + 1) * OSTR + nb + 8] = o[mt][mq][nq][3];
                }
            }
        }
    }
#pragma unroll
    for (int mq = 0; mq < 2; mq++) {
        float r0 = rsv[mq][0], r1 = rsv[mq][1];
        r0 += __shfl_xor_sync(0xffffffffu, r0, 1);
        r0 += __shfl_xor_sync(0xffffffffu, r0, 2);
        r1 += __shfl_xor_sync(0xffffffffu, r1, 1);
        r1 += __shfl_xor_sync(0xffffffffu, r1, 2);
        if (j == 0) {
            atomicAdd(&rs[wm * 32 + mq * 16 + g], r0);
            atomicAdd(&rs[wm * 32 + mq * 16 + 8 + g], r1);
        }
    }
    __syncthreads();
    if (tid < 128) {
        float inv = 1.0f / rs[tid];
        g_rinv[(size_t)hb * S_ + q0 + tid] = inv;
        rs[tid] = inv;
    }
    __syncthreads();

    const float* vc = g_vcs + (b * H_ + h) * 64;
#pragma unroll
    for (int i = 0; i < 32; i++) {
        int lin = tid + i * 256;
        int qr  = lin >> 6;
        int d   = lin & 63;
        float val = (Obuf[qr * OSTR + d] + Obuf[128 * OSTR + qr * OSTR + d] + vc[d]) * rs[qr];
        g_ctx[((size_t)(b * S_ + q0 + qr)) * D_ + h * 64 + d] = val;
    }
}

// ---------------------------------------------------------------------------
// Normalize attn in place: attn[hb][q][k] *= g_rinv[hb*S+q]
// ---------------------------------------------------------------------------
__global__ __launch_bounds__(256) void attn_norm(float* __restrict__ attn) {
    size_t i = (size_t)blockIdx.x * 256 + threadIdx.x;  // float4 index
    float inv = g_rinv[i >> 9];                          // 512 float4 per row
    float4* p = (float4*)attn;
    float4 v = p[i];
    v.x *= inv; v.y *= inv; v.z *= inv; v.w *= inv;
    p[i] = v;
}

// ---------------------------------------------------------------------------
// LayerNorm over rows of g_dense -> out
// ---------------------------------------------------------------------------
__global__ __launch_bounds__(256) void ln_kernel(const float* __restrict__ lg,
                                                 const float* __restrict__ lb,
                                                 float* __restrict__ out) {
    const int row = blockIdx.x;
    const int tid = threadIdx.x;
    const float* x = g_dense + (size_t)row * 1024;
    float4 xv = *(const float4*)(x + tid * 4);
    float s  = xv.x + xv.y + xv.z + xv.w;
    float ss = fmaf(xv.x, xv.x, fmaf(xv.y, xv.y, fmaf(xv.z, xv.z, xv.w * xv.w)));
#pragma unroll
    for (int off = 16; off > 0; off >>= 1) {
        s  += __shfl_xor_sync(0xffffffffu, s, off);
        ss += __shfl_xor_sync(0xffffffffu, ss, off);
    }
    __shared__ float sm1[8], sm2[8];
    if ((tid & 31) == 0) { sm1[tid >> 5] = s; sm2[tid >> 5] = ss; }
    __syncthreads();
    if (tid < 32) {
        float a  = (tid < 8) ? sm1[tid] : 0.f;
        float b2 = (tid < 8) ? sm2[tid] : 0.f;
#pragma unroll
        for (int off = 4; off > 0; off >>= 1) {
            a  += __shfl_xor_sync(0xffffffffu, a, off);
            b2 += __shfl_xor_sync(0xffffffffu, b2, off);
        }
        if (tid == 0) { sm1[0] = a; sm2[0] = b2; }
    }
    __syncthreads();
    float mean = sm1[0] * (1.0f / 1024.0f);
    float var  = sm2[0] * (1.0f / 1024.0f) - mean * mean;
    float rstd = rsqrtf(var + 1e-5f);
    float4 gv = *(const float4*)(lg + tid * 4);
    float4 bv = *(const float4*)(lb + tid * 4);
    float4 ov;
    ov.x = (xv.x - mean) * rstd * gv.x + bv.x;
    ov.y = (xv.y - mean) * rstd * gv.y + bv.y;
    ov.z = (xv.z - mean) * rstd * gv.z + bv.z;
    ov.w = (xv.w - mean) * rstd * gv.w + bv.w;
    *(float4*)(out + (size_t)row * 1024 + tid * 4) = ov;
}

// ---------------------------------------------------------------------------
// Launch (7 launches; attn is #4 so the harness ncu capture samples it)
// ---------------------------------------------------------------------------
extern "C" void kernel_launch(void* const* d_in, const int* in_sizes, int n_in,
                              void* d_out, int out_size) {
    const float* k_in = (const float*)d_in[0];
    const float* q_in = (const float*)d_in[1];
    const float* wk   = (const float*)d_in[2];
    const float* bk   = (const float*)d_in[3];
    const float* wq   = (const float*)d_in[4];
    const float* bq   = (const float*)d_in[5];
    const float* wv   = (const float*)d_in[6];
    const float* bv   = (const float*)d_in[7];
    const float* wd   = (const float*)d_in[8];
    const float* bd   = (const float*)d_in[9];
    const float* lg   = (const float*)d_in[10];
    const float* lb   = (const float*)d_in[11];

    float* out  = (float*)d_out;
    float* attn = out + (size_t)B_ * S_ * D_;  // tuple order: (out, attn)

    const int attn_smem_bytes = ATTN_SMEM_FLOATS * 4;  // 111104 B
    cudaFuncSetAttribute(attn_kernel, cudaFuncAttributeMaxDynamicSharedMemorySize,
                         attn_smem_bytes);

    dim3 pgrid(MTOT / 128, D_ / 128);  // (32, 8)
    qkv_gemm<<<pgrid, 256>>>(q_in, wq, bq, 0);   // g_qx (permuted) + zero g_vcs
    qkv_gemm<<<pgrid, 256>>>(k_in, wk, bk, 1);   // g_kx (permuted)
    qkv_gemm<<<pgrid, 256>>>(k_in, wv, bv, 2);   // g_vx + colsums (v = k)

    attn_kernel<<<dim3(S_ / 128, HB_), 256, attn_smem_bytes>>>(attn);

    attn_norm<<<131072, 256>>>(attn);

    dense_gemm<<<pgrid, 256>>>(wd, bd);          // dense + relu -> g_dense
    ln_kernel<<<MTOT, 256>>>(lg, lb, out);
}

// round 16
// speedup vs baseline: 1.0209x; 1.0188x over previous
#include <cuda_runtime.h>
#include <cstdint>
#include <cstddef>

// Problem constants
#define B_    2
#define S_    2048
#define D_    1024
#define H_    16
#define DK_   64
#define MTOT  4096        // B_*S_
#define HB_   32          // H_*B_

// ---------------------------------------------------------------------------
// Scratch (static device allocations; no dynamic alloc allowed)
// g_qx / g_kx store the dk axis PERMUTED: dk' = (dk&56)|((dk&3)<<1)|((dk>>2)&1)
// (scores invariant; enables paired LDS.64 B-fragment loads in attn).
// g_vx is natural layout (PV + colsum need it).
// ---------------------------------------------------------------------------
static __device__ float g_qx[B_ * H_ * S_ * DK_];   // [b][h][s][dk']
static __device__ float g_kx[B_ * H_ * S_ * DK_];   // [b][h][s][dk']
static __device__ float g_vx[B_ * H_ * S_ * DK_];   // [b][h][s][dk]
static __device__ float g_ctx[(size_t)MTOT * D_];   // [b*S+s][h*64+dk]
static __device__ float g_dense[(size_t)MTOT * D_];
static __device__ float g_rinv[HB_ * S_];           // 1/rowsum per attn row
static __device__ float g_vcs[HB_ * DK_];           // colsum of V per (b*H+h, d)

// ---------------------------------------------------------------------------
// Helpers
// ---------------------------------------------------------------------------
__device__ __forceinline__ float tf32_hi(float x) {
    uint32_t r;
    asm("cvt.rna.tf32.f32 %0, %1;" : "=r"(r) : "f"(x));
    return __uint_as_float(r);
}

__device__ __forceinline__ void mma_tf32(float c[4],
                                         uint32_t a0, uint32_t a1, uint32_t a2, uint32_t a3,
                                         uint32_t b0, uint32_t b1) {
    asm volatile(
        "mma.sync.aligned.m16n8k8.row.col.f32.tf32.tf32.f32 "
        "{%0,%1,%2,%3}, {%4,%5,%6,%7}, {%8,%9}, {%0,%1,%2,%3};\n"
        : "+f"(c[0]), "+f"(c[1]), "+f"(c[2]), "+f"(c[3])
        : "r"(a0), "r"(a1), "r"(a2), "r"(a3), "r"(b0), "r"(b1));
}

__device__ __forceinline__ void cp_async16(uint32_t smem_addr, const void* gptr) {
    asm volatile("cp.async.cg.shared.global [%0], [%1], 16;"
                 :: "r"(smem_addr), "l"(gptr));
}

// ---------------------------------------------------------------------------
// QKV projection GEMM (1xTF32, cp.async double-buffered raw staging).
// mode 0 -> g_qx (permuted dk, also zeroes g_vcs), mode 1 -> g_kx (permuted),
// mode 2 -> g_vx (natural dk, accumulates g_vcs colsums via atomics).
// ---------------------------------------------------------------------------
__global__ __launch_bounds__(256) void qkv_gemm(const float* __restrict__ A,
                                                const float* __restrict__ W,
                                                const float* __restrict__ bias,
                                                int mode) {
    __shared__ float As[2][128 * 20];
    __shared__ float Bs[2][128 * 20];

    const int tid  = threadIdx.x;
    const int lane = tid & 31;
    const int warp = tid >> 5;
    const int wm   = warp & 1;
    const int wn   = warp >> 1;
    const int m0   = blockIdx.x * 128;
    const int n0   = blockIdx.y * 128;

    if (mode == 0 && blockIdx.x == 0 && blockIdx.y == 0) {
#pragma unroll
        for (int i = 0; i < 8; i++) g_vcs[tid + i * 256] = 0.f;
    }

    const int r0 = tid >> 2;
    const int c0 = (tid & 3) * 4;

    float c[4][4][4];
#pragma unroll
    for (int i = 0; i < 4; i++)
#pragma unroll
        for (int j = 0; j < 4; j++)
#pragma unroll
            for (int k = 0; k < 4; k++) c[i][j][k] = 0.f;

    {
        uint32_t as = (uint32_t)__cvta_generic_to_shared(&As[0][0]);
        uint32_t bs = (uint32_t)__cvta_generic_to_shared(&Bs[0][0]);
#pragma unroll
        for (int i = 0; i < 2; i++) {
            int r = r0 + i * 64;
            cp_async16(as + (r * 20 + c0) * 4, A + (size_t)(m0 + r) * 1024 + c0);
            cp_async16(bs + (r * 20 + c0) * 4, W + (size_t)(n0 + r) * 1024 + c0);
        }
        asm volatile("cp.async.commit_group;");
    }

    for (int kt = 0; kt < 64; kt++) {
        asm volatile("cp.async.wait_group 0;");
        __syncthreads();

        if (kt + 1 < 64) {
            int buf = (kt + 1) & 1;
            int k0  = (kt + 1) * 16;
            uint32_t as = (uint32_t)__cvta_generic_to_shared(&As[buf][0]);
            uint32_t bs = (uint32_t)__cvta_generic_to_shared(&Bs[buf][0]);
#pragma unroll
            for (int i = 0; i < 2; i++) {
                int r = r0 + i * 64;
                cp_async16(as + (r * 20 + c0) * 4, A + (size_t)(m0 + r) * 1024 + k0 + c0);
                cp_async16(bs + (r * 20 + c0) * 4, W + (size_t)(n0 + r) * 1024 + k0 + c0);
            }
            asm volatile("cp.async.commit_group;");
        }

        const float* Ab = As[kt & 1];
        const float* Bb = Bs[kt & 1];
#pragma unroll
        for (int kg = 0; kg < 16; kg += 8) {
            uint32_t bh[4][2];
#pragma unroll
            for (int nt = 0; nt < 4; nt++) {
                int boff = (wn * 32 + nt * 8 + (lane >> 2)) * 20 + kg + (lane & 3);
                bh[nt][0] = __float_as_uint(Bb[boff]);
                bh[nt][1] = __float_as_uint(Bb[boff + 4]);
            }
#pragma unroll
            for (int mt = 0; mt < 4; mt++) {
                int aoff = (wm * 64 + mt * 16 + (lane >> 2)) * 20 + kg + (lane & 3);
                uint32_t a0 = __float_as_uint(Ab[aoff]);
                uint32_t a1 = __float_as_uint(Ab[aoff + 8 * 20]);
                uint32_t a2 = __float_as_uint(Ab[aoff + 4]);
                uint32_t a3 = __float_as_uint(Ab[aoff + 8 * 20 + 4]);
#pragma unroll
                for (int nt = 0; nt < 4; nt++)
                    mma_tf32(c[mt][nt], a0, a1, a2, a3, bh[nt][0], bh[nt][1]);
            }
        }
    }

    __syncthreads();

    float csum[4][2];
#pragma unroll
    for (int nt = 0; nt < 4; nt++) { csum[nt][0] = 0.f; csum[nt][1] = 0.f; }

#pragma unroll
    for (int mt = 0; mt < 4; mt++) {
#pragma unroll
        for (int nt = 0; nt < 4; nt++) {
#pragma unroll
            for (int j = 0; j < 4; j++) {
                int row = m0 + wm * 64 + mt * 16 + (lane >> 2) + ((j >> 1) << 3);
                int col = n0 + wn * 32 + nt * 8 + 2 * (lane & 3) + (j & 1);
                float v = c[mt][nt][j] + bias[col];
                int b  = row >> 11;
                int s  = row & 2047;
                int h  = col >> 6;
                int dk = col & 63;
                if (mode == 2) {
                    csum[nt][j & 1] += v;
                    g_vx[(((size_t)(b * H_ + h)) * S_ + s) * DK_ + dk] = v;
                } else {
                    int dkp = (dk & 56) | ((dk & 3) << 1) | ((dk >> 2) & 1);
                    float* dst = (mode == 0) ? g_qx : g_kx;
                    dst[(((size_t)(b * H_ + h)) * S_ + s) * DK_ + dkp] = v;
                }
            }
        }
    }

    if (mode == 2) {
#pragma unroll
        for (int nt = 0; nt < 4; nt++) {
#pragma unroll
            for (int p = 0; p < 2; p++) {
                float v = csum[nt][p];
                v += __shfl_down_sync(0xffffffffu, v, 16);
                v += __shfl_down_sync(0xffffffffu, v, 8);
                v += __shfl_down_sync(0xffffffffu, v, 4);
                if (lane < 4) {
                    int col = n0 + wn * 32 + nt * 8 + 2 * lane + p;
                    int b   = m0 >> 11;
                    int bh  = b * H_ + (col >> 6);
                    atomicAdd(&g_vcs[bh * 64 + (col & 63)], v);
                }
            }
        }
    }
}

// ---------------------------------------------------------------------------
// Dense GEMM (3xTF32 RN via register hi/lo split; cp.async raw staging) FUSED
// with the attn normalization stream: each block normalizes a 131072-float4
// slice of attn (2048 float4 per kt iteration), overlapping DRAM streaming
// with the tensor-bound GEMM.  g_dense = relu(g_ctx @ dense_w^T + dense_b);
// attn[i] *= g_rinv[row(i)].
// ---------------------------------------------------------------------------
__global__ __launch_bounds__(256) void dense_gemm(const float* __restrict__ W,
                                                  const float* __restrict__ bias,
                                                  float* __restrict__ attn) {
    __shared__ float As[2][128 * 20];
    __shared__ float Bs[2][128 * 20];

    const float* Ap = g_ctx;

    const int tid  = threadIdx.x;
    const int lane = tid & 31;
    const int warp = tid >> 5;
    const int wm   = warp & 1;
    const int wn   = warp >> 1;
    const int m0   = blockIdx.x * 128;
    const int n0   = blockIdx.y * 128;

    const int r0 = tid >> 2;
    const int c0 = (tid & 3) * 4;

    // norm slice for this block: 131072 float4 (256 blocks cover 2^25 float4)
    const int bid = blockIdx.y * 32 + blockIdx.x;
    float4* ap = (float4*)attn;
    const size_t nbase = (size_t)bid * 131072;

    float c[4][4][4];
#pragma unroll
    for (int i = 0; i < 4; i++)
#pragma unroll
        for (int j = 0; j < 4; j++)
#pragma unroll
            for (int k = 0; k < 4; k++) c[i][j][k] = 0.f;

    {
        uint32_t as = (uint32_t)__cvta_generic_to_shared(&As[0][0]);
        uint32_t bs = (uint32_t)__cvta_generic_to_shared(&Bs[0][0]);
#pragma unroll
        for (int i = 0; i < 2; i++) {
            int r = r0 + i * 64;
            cp_async16(as + (r * 20 + c0) * 4, Ap + (size_t)(m0 + r) * 1024 + c0);
            cp_async16(bs + (r * 20 + c0) * 4, W + (size_t)(n0 + r) * 1024 + c0);
        }
        asm volatile("cp.async.commit_group;");
    }

    for (int kt = 0; kt < 64; kt++) {
        asm volatile("cp.async.wait_group 0;");
        __syncthreads();

        if (kt + 1 < 64) {
            int buf = (kt + 1) & 1;
            int k0  = (kt + 1) * 16;
            uint32_t as = (uint32_t)__cvta_generic_to_shared(&As[buf][0]);
            uint32_t bs = (uint32_t)__cvta_generic_to_shared(&Bs[buf][0]);
#pragma unroll
            for (int i = 0; i < 2; i++) {
                int r = r0 + i * 64;
                cp_async16(as + (r * 20 + c0) * 4, Ap + (size_t)(m0 + r) * 1024 + k0 + c0);
                cp_async16(bs + (r * 20 + c0) * 4, W + (size_t)(n0 + r) * 1024 + k0 + c0);
            }
            asm volatile("cp.async.commit_group;");
        }

        // attn normalization chunk for this kt: 2048 float4, coalesced.
        // Dependent LDG->STG; stalls here overlap other warps' MMA issue.
        {
            size_t base = nbase + (size_t)kt * 2048 + tid;
#pragma unroll
            for (int i = 0; i < 8; i++) {
                size_t idx = base + (size_t)i * 256;
                float inv = g_rinv[idx >> 9];    // 512 float4 per attn row
                float4 v = ap[idx];
                v.x *= inv; v.y *= inv; v.z *= inv; v.w *= inv;
                ap[idx] = v;
            }
        }

        const float* Ab = As[kt & 1];
        const float* Bb = Bs[kt & 1];
#pragma unroll
        for (int kg = 0; kg < 16; kg += 8) {
            uint32_t bh[4][2], bl[4][2];
#pragma unroll
            for (int nt = 0; nt < 4; nt++) {
                int boff = (wn * 32 + nt * 8 + (lane >> 2)) * 20 + kg + (lane & 3);
                float rb0 = Bb[boff];
                float rb1 = Bb[boff + 4];
                float hb0 = tf32_hi(rb0);
                float hb1 = tf32_hi(rb1);
                bh[nt][0] = __float_as_uint(hb0);
                bh[nt][1] = __float_as_uint(hb1);
                bl[nt][0] = __float_as_uint(rb0 - hb0);
                bl[nt][1] = __float_as_uint(rb1 - hb1);
            }
#pragma unroll
            for (int mt = 0; mt < 4; mt++) {
                int aoff = (wm * 64 + mt * 16 + (lane >> 2)) * 20 + kg + (lane & 3);
                float ra0 = Ab[aoff];
                float ra1 = Ab[aoff + 8 * 20];
                float ra2 = Ab[aoff + 4];
                float ra3 = Ab[aoff + 8 * 20 + 4];
                float ha0 = tf32_hi(ra0), ha1 = tf32_hi(ra1);
                float ha2 = tf32_hi(ra2), ha3 = tf32_hi(ra3);
                uint32_t ah0 = __float_as_uint(ha0), ah1 = __float_as_uint(ha1);
                uint32_t ah2 = __float_as_uint(ha2), ah3 = __float_as_uint(ha3);
                uint32_t al0 = __float_as_uint(ra0 - ha0), al1 = __float_as_uint(ra1 - ha1);
                uint32_t al2 = __float_as_uint(ra2 - ha2), al3 = __float_as_uint(ra3 - ha3);
#pragma unroll
                for (int nt = 0; nt < 4; nt++) {
                    mma_tf32(c[mt][nt], ah0, ah1, ah2, ah3, bh[nt][0], bh[nt][1]);
                    mma_tf32(c[mt][nt], ah0, ah1, ah2, ah3, bl[nt][0], bl[nt][1]);
                    mma_tf32(c[mt][nt], al0, al1, al2, al3, bh[nt][0], bh[nt][1]);
                }
            }
        }
    }

    __syncthreads();
#pragma unroll
    for (int mt = 0; mt < 4; mt++) {
#pragma unroll
        for (int nt = 0; nt < 4; nt++) {
#pragma unroll
            for (int j = 0; j < 4; j++) {
                int row = m0 + wm * 64 + mt * 16 + (lane >> 2) + ((j >> 1) << 3);
                int col = n0 + wn * 32 + nt * 8 + 2 * (lane & 3) + (j & 1);
                float v = c[mt][nt][j] + bias[col];
                g_dense[(size_t)row * 1024 + col] = v > 0.f ? v : 0.f;
            }
        }
    }
}

// ---------------------------------------------------------------------------
// Fused attention kernel (v7: 32 q-rows/warp, 128 q-rows/block, 3-stage
// cp.async pipeline; PV transposed with shuffle-fed dp).
// grid = (S/128, H*B), block = 256 (8 warps: wm 0..3 = 32 q-rows, wn 0..1 =
// kv half). 1 CTA/SM.
// ---------------------------------------------------------------------------
#define KSTR 72
#define VSTR 72
#define KVBUF (64 * KSTR + 64 * VSTR)   // 9216 floats per buffer
#define NSTAGE 3
#define OSTR 66
#define ATTN_SMEM_FLOATS (NSTAGE * KVBUF + 128)   // 27776 floats = 111104 B

__global__ __launch_bounds__(256, 1) void attn_kernel(float* __restrict__ attn_out) {
    extern __shared__ float smf[];
    float* rs   = smf + NSTAGE * KVBUF;      // rowsum[128]
    float* Obuf = smf;                       // epilogue alias: 2 x 128 x 66 (16896 <= 27648)

    const int tid  = threadIdx.x;
    const int lane = tid & 31;
    const int warp = tid >> 5;
    const int wm   = warp & 3;               // q-row group (32 rows each)
    const int wn   = warp >> 2;              // kv half
    const int g    = lane >> 2;
    const int j    = lane & 3;
    const int hb   = blockIdx.y;             // h*B + b
    const int h    = hb >> 1;
    const int b    = hb & 1;
    const int q0   = blockIdx.x * 128;

    const float* qbase = g_qx + ((size_t)(b * H_ + h)) * S_ * DK_;
    const float* kbase = g_kx + ((size_t)(b * H_ + h)) * S_ * DK_;
    const float* vbase = g_vx + ((size_t)(b * H_ + h)) * S_ * DK_;
    const float invT = 0.03125f;             // 1/sqrt(1024)

    if (tid < 128) rs[tid] = 0.f;

    const int sr  = tid >> 4;                // base row 0..15 (+16 per i)
    const int sc4 = (tid & 15) * 4;          // col 0..60

    // prologue: issue tiles 0 and 1 (two commit groups)
#pragma unroll
    for (int t = 0; t < 2; t++) {
        float* Kb = smf + t * KVBUF;
        float* Vb = Kb + 64 * KSTR;
        uint32_t ksm = (uint32_t)__cvta_generic_to_shared(Kb);
        uint32_t vsm = (uint32_t)__cvta_generic_to_shared(Vb);
        const float* kb = kbase + (size_t)t * 64 * 64;
        const float* vb = vbase + (size_t)t * 64 * 64;
#pragma unroll
        for (int i = 0; i < 4; i++) {
            int r = sr + i * 16;
            cp_async16(ksm + (r * KSTR + sc4) * 4, kb + (size_t)r * 64 + sc4);
            cp_async16(vsm + (r * VSTR + sc4) * 4, vb + (size_t)r * 64 + sc4);
        }
        asm volatile("cp.async.commit_group;");
    }

    // Q fragments in registers (RN tf32, pre-scaled), permuted layout;
    // two 16-row m-tiles per warp (mq = 0, 1).
    uint32_t qa[2][8][4];
#pragma unroll
    for (int mq = 0; mq < 2; mq++) {
        const float* qr0 = qbase + (size_t)(q0 + wm * 32 + mq * 16 + g) * 64;
        const float* qr1 = qr0 + 8 * 64;
#pragma unroll
        for (int kg = 0; kg < 8; kg++) {
            float2 u0 = *(const float2*)(qr0 + kg * 8 + 2 * j);
            float2 u1 = *(const float2*)(qr1 + kg * 8 + 2 * j);
            qa[mq][kg][0] = __float_as_uint(tf32_hi(u0.x * invT));
            qa[mq][kg][2] = __float_as_uint(tf32_hi(u0.y * invT));
            qa[mq][kg][1] = __float_as_uint(tf32_hi(u1.x * invT));
            qa[mq][kg][3] = __float_as_uint(tf32_hi(u1.y * invT));
        }
    }

    // O' accumulators: o[mt][mq][nq][c] -> O'[n = mt*16+g(+8)][q tile mq*16+nq*8]
    float o[4][2][2][4];
#pragma unroll
    for (int mt = 0; mt < 4; mt++)
#pragma unroll
        for (int mq = 0; mq < 2; mq++)
#pragma unroll
            for (int nq = 0; nq < 2; nq++)
#pragma unroll
                for (int k = 0; k < 4; k++) o[mt][mq][nq][k] = 0.f;
    float rsv[2][2] = {{0.f, 0.f}, {0.f, 0.f}};

    const int src0 = 4 * g + (j >> 1);       // shuffle source lanes
    const int src1 = src0 + 2;
    const bool jodd = (j & 1) != 0;

    int buf = 0;                             // buffer of tile kt (kt % 3)
    for (int kt = 0; kt < 32; kt++) {
        float* Kb = smf + buf * KVBUF;
        float* Vb = Kb + 64 * KSTR;

        // steady state: allow 1 group (tile kt+1) outstanding; tail: drain all
        if (kt < 30) {
            asm volatile("cp.async.wait_group 1;");
        } else {
            asm volatile("cp.async.wait_group 0;");
        }
        __syncthreads();

        if (kt + 2 < 32) {
            int nbuf = buf + 2;
            if (nbuf >= NSTAGE) nbuf -= NSTAGE;
            float* Kn = smf + nbuf * KVBUF;
            float* Vn = Kn + 64 * KSTR;
            uint32_t ksm = (uint32_t)__cvta_generic_to_shared(Kn);
            uint32_t vsm = (uint32_t)__cvta_generic_to_shared(Vn);
            const float* kb = kbase + (size_t)(kt + 2) * 64 * 64;
            const float* vb = vbase + (size_t)(kt + 2) * 64 * 64;
#pragma unroll
            for (int i = 0; i < 4; i++) {
                int r = sr + i * 16;
                cp_async16(ksm + (r * KSTR + sc4) * 4, kb + (size_t)r * 64 + sc4);
                cp_async16(vsm + (r * VSTR + sc4) * 4, vb + (size_t)r * 64 + sc4);
            }
            asm volatile("cp.async.commit_group;");
        }

        // scores: K B-frags loaded once per kg, reused by both mq tiles
        float s[2][4][4];
#pragma unroll
        for (int mq = 0; mq < 2; mq++)
#pragma unroll
            for (int i = 0; i < 4; i++)
#pragma unroll
                for (int k = 0; k < 4; k++) s[mq][i][k] = 0.f;
#pragma unroll
        for (int kg = 0; kg < 8; kg++) {
            float2 kb2[4];
#pragma unroll
            for (int nt = 0; nt < 4; nt++)
                kb2[nt] = *(const float2*)(Kb + (wn * 32 + nt * 8 + g) * KSTR + kg * 8 + 2 * j);
#pragma unroll
            for (int mq = 0; mq < 2; mq++)
#pragma unroll
                for (int nt = 0; nt < 4; nt++)
                    mma_tf32(s[mq][nt], qa[mq][kg][0], qa[mq][kg][1],
                             qa[mq][kg][2], qa[mq][kg][3],
                             __float_as_uint(kb2[nt].x), __float_as_uint(kb2[nt].y));
        }

        // exp -> gmem attn (unnormalized), rowsum regs; dp overwrites s[][][]
        const int k0 = kt * 64;
#pragma unroll
        for (int mq = 0; mq < 2; mq++) {
            float* ab = attn_out +
                ((size_t)hb * S_ + q0 + wm * 32 + mq * 16 + g) * S_ + k0 + wn * 32;
#pragma unroll
            for (int nt = 0; nt < 4; nt++) {
                float p0 = __expf(s[mq][nt][0]);
                float p1 = __expf(s[mq][nt][1]);
                float p2 = __expf(s[mq][nt][2]);
                float p3 = __expf(s[mq][nt][3]);
                rsv[mq][0] += p0 + p1;
                rsv[mq][1] += p2 + p3;
                *(float2*)(ab + nt * 8 + 2 * j) = make_float2(p0, p1);
                *(float2*)(ab + (size_t)8 * S_ + nt * 8 + 2 * j) = make_float2(p2, p3);
                s[mq][nt][0] = p0 - 1.f;
                s[mq][nt][1] = p1 - 1.f;
                s[mq][nt][2] = p2 - 1.f;
                s[mq][nt][3] = p3 - 1.f;
            }
        }

        // PV (transposed): O'[n][q] += V'[n][k] * dp'[k][q]
        // A-frags = V columns (loaded once per kp, reused by all 4 q-subtiles)
#pragma unroll
        for (int kp = 0; kp < 4; kp++) {
            uint32_t av[4][4];
#pragma unroll
            for (int mt = 0; mt < 4; mt++) {
                int aoff = (wn * 32 + kp * 8 + j) * VSTR + mt * 16 + g;
                av[mt][0] = __float_as_uint(Vb[aoff]);
                av[mt][1] = __float_as_uint(Vb[aoff + 8]);
                av[mt][2] = __float_as_uint(Vb[aoff + 4 * VSTR]);
                av[mt][3] = __float_as_uint(Vb[aoff + 4 * VSTR + 8]);
            }
#pragma unroll
            for (int mq = 0; mq < 2; mq++) {
#pragma unroll
                for (int nq = 0; nq < 2; nq++) {
                    float v00 = __shfl_sync(0xffffffffu, s[mq][kp][2 * nq + 0], src0);
                    float v01 = __shfl_sync(0xffffffffu, s[mq][kp][2 * nq + 1], src0);
                    float v10 = __shfl_sync(0xffffffffu, s[mq][kp][2 * nq + 0], src1);
                    float v11 = __shfl_sync(0xffffffffu, s[mq][kp][2 * nq + 1], src1);
                    uint32_t b0 = __float_as_uint(jodd ? v01 : v00);
                    uint32_t b1 = __float_as_uint(jodd ? v11 : v10);
#pragma unroll
                    for (int mt = 0; mt < 4; mt++)
                        mma_tf32(o[mt][mq][nq], av[mt][0], av[mt][1], av[mt][2], av[mt][3],
                                 b0, b1);
                }
            }
        }

        buf++;
        if (buf == NSTAGE) buf = 0;
    }

    // --- epilogue ---
    __syncthreads();   // all PV reads of the KV buffers complete before aliasing
    {
        float* Ob = Obuf + wn * 128 * OSTR;
#pragma unroll
        for (int mt = 0; mt < 4; mt++) {
#pragma unroll
            for (int mq = 0; mq < 2; mq++) {
#pragma unroll
                for (int nq = 0; nq < 2; nq++) {
                    int qb = wm * 32 + mq * 16 + nq * 8 + 2 * j;
                    int nb = mt * 16 + g;
                    Ob[qb * OSTR + nb]           = o[mt][mq][nq][0];
                    Ob[(qb + 1) * OSTR + nb]     = o[mt][mq][nq][1];
                    Ob[qb * OSTR + nb + 8]       = o[mt][mq][nq][2];
                    Ob[(qb + 1) * OSTR + nb + 8] = o[mt][mq][nq][3];
                }
            }
        }
    }
#pragma unroll
    for (int mq = 0; mq < 2; mq++) {
        float r0 = rsv[mq][0], r1 = rsv[mq][1];
        r0 += __shfl_xor_sync(0xffffffffu, r0, 1);
        r0 += __shfl_xor_sync(0xffffffffu, r0, 2);
        r1 += __shfl_xor_sync(0xffffffffu, r1, 1);
        r1 += __shfl_xor_sync(0xffffffffu, r1, 2);
        if (j == 0) {
            atomicAdd(&rs[wm * 32 + mq * 16 + g], r0);
            atomicAdd(&rs[wm * 32 + mq * 16 + 8 + g], r1);
        }
    }
    __syncthreads();
    if (tid < 128) {
        float inv = 1.0f / rs[tid];
        g_rinv[(size_t)hb * S_ + q0 + tid] = inv;
        rs[tid] = inv;
    }
    __syncthreads();

    const float* vc = g_vcs + (b * H_ + h) * 64;
#pragma unroll
    for (int i = 0; i < 32; i++) {
        int lin = tid + i * 256;
        int qr  = lin >> 6;
        int d   = lin & 63;
        float val = (Obuf[qr * OSTR + d] + Obuf[128 * OSTR + qr * OSTR + d] + vc[d]) * rs[qr];
        g_ctx[((size_t)(b * S_ + q0 + qr)) * D_ + h * 64 + d] = val;
    }
}

// ---------------------------------------------------------------------------
// LayerNorm over rows of g_dense -> out
// ---------------------------------------------------------------------------
__global__ __launch_bounds__(256) void ln_kernel(const float* __restrict__ lg,
                                                 const float* __restrict__ lb,
                                                 float* __restrict__ out) {
    const int row = blockIdx.x;
    const int tid = threadIdx.x;
    const float* x = g_dense + (size_t)row * 1024;
    float4 xv = *(const float4*)(x + tid * 4);
    float s  = xv.x + xv.y + xv.z + xv.w;
    float ss = fmaf(xv.x, xv.x, fmaf(xv.y, xv.y, fmaf(xv.z, xv.z, xv.w * xv.w)));
#pragma unroll
    for (int off = 16; off > 0; off >>= 1) {
        s  += __shfl_xor_sync(0xffffffffu, s, off);
        ss += __shfl_xor_sync(0xffffffffu, ss, off);
    }
    __shared__ float sm1[8], sm2[8];
    if ((tid & 31) == 0) { sm1[tid >> 5] = s; sm2[tid >> 5] = ss; }
    __syncthreads();
    if (tid < 32) {
        float a  = (tid < 8) ? sm1[tid] : 0.f;
        float b2 = (tid < 8) ? sm2[tid] : 0.f;
#pragma unroll
        for (int off = 4; off > 0; off >>= 1) {
            a  += __shfl_xor_sync(0xffffffffu, a, off);
            b2 += __shfl_xor_sync(0xffffffffu, b2, off);
        }
        if (tid == 0) { sm1[0] = a; sm2[0] = b2; }
    }
    __syncthreads();
    float mean = sm1[0] * (1.0f / 1024.0f);
    float var  = sm2[0] * (1.0f / 1024.0f) - mean * mean;
    float rstd = rsqrtf(var + 1e-5f);
    float4 gv = *(const float4*)(lg + tid * 4);
    float4 bv = *(const float4*)(lb + tid * 4);
    float4 ov;
    ov.x = (xv.x - mean) * rstd * gv.x + bv.x;
    ov.y = (xv.y - mean) * rstd * gv.y + bv.y;
    ov.z = (xv.z - mean) * rstd * gv.z + bv.z;
    ov.w = (xv.w - mean) * rstd * gv.w + bv.w;
    *(float4*)(out + (size_t)row * 1024 + tid * 4) = ov;
}

// ---------------------------------------------------------------------------
// Launch (6 launches; attn is #4 so the harness ncu capture samples it)
// ---------------------------------------------------------------------------
extern "C" void kernel_launch(void* const* d_in, const int* in_sizes, int n_in,
                              void* d_out, int out_size) {
    const float* k_in = (const float*)d_in[0];
    const float* q_in = (const float*)d_in[1];
    const float* wk   = (const float*)d_in[2];
    const float* bk   = (const float*)d_in[3];
    const float* wq   = (const float*)d_in[4];
    const float* bq   = (const float*)d_in[5];
    const float* wv   = (const float*)d_in[6];
    const float* bv   = (const float*)d_in[7];
    const float* wd   = (const float*)d_in[8];
    const float* bd   = (const float*)d_in[9];
    const float* lg   = (const float*)d_in[10];
    const float* lb   = (const float*)d_in[11];

    float* out  = (float*)d_out;
    float* attn = out + (size_t)B_ * S_ * D_;  // tuple order: (out, attn)

    const int attn_smem_bytes = ATTN_SMEM_FLOATS * 4;  // 111104 B
    cudaFuncSetAttribute(attn_kernel, cudaFuncAttributeMaxDynamicSharedMemorySize,
                         attn_smem_bytes);

    dim3 pgrid(MTOT / 128, D_ / 128);  // (32, 8)
    qkv_gemm<<<pgrid, 256>>>(q_in, wq, bq, 0);   // g_qx (permuted) + zero g_vcs
    qkv_gemm<<<pgrid, 256>>>(k_in, wk, bk, 1);   // g_kx (permuted)
    qkv_gemm<<<pgrid, 256>>>(k_in, wv, bv, 2);   // g_vx + colsums (v = k)

    attn_kernel<<<dim3(S_ / 128, HB_), 256, attn_smem_bytes>>>(attn);

    dense_gemm<<<pgrid, 256>>>(wd, bd, attn);    // dense + relu + attn norm
    ln_kernel<<<MTOT, 256>>>(lg, lb, out);
}

// round 17
// speedup vs baseline: 1.0399x; 1.0186x over previous
#include <cuda_runtime.h>
#include <cstdint>
#include <cstddef>

// Problem constants
#define B_    2
#define S_    2048
#define D_    1024
#define H_    16
#define DK_   64
#define MTOT  4096        // B_*S_
#define HB_   32          // H_*B_

// ---------------------------------------------------------------------------
// Scratch (static device allocations; no dynamic alloc allowed)
// g_qx / g_kx store the dk axis PERMUTED: dk' = (dk&56)|((dk&3)<<1)|((dk>>2)&1)
// g_vx is natural layout. g_vcsp holds race-free V-colsum partials:
// slot (xblk&15)*2+wm, fully overwritten every run (graph-replay safe).
// ---------------------------------------------------------------------------
static __device__ float g_qx[B_ * H_ * S_ * DK_];   // [b][h][s][dk']
static __device__ float g_kx[B_ * H_ * S_ * DK_];   // [b][h][s][dk']
static __device__ float g_vx[B_ * H_ * S_ * DK_];   // [b][h][s][dk]
static __device__ float g_ctx[(size_t)MTOT * D_];   // [b*S+s][h*64+dk]
static __device__ float g_dense[(size_t)MTOT * D_];
static __device__ float g_rinv[HB_ * S_];           // 1/rowsum per attn row
static __device__ float g_vcsp[32][HB_ * DK_];      // V colsum partials

// ---------------------------------------------------------------------------
// Helpers
// ---------------------------------------------------------------------------
__device__ __forceinline__ float tf32_hi(float x) {
    uint32_t r;
    asm("cvt.rna.tf32.f32 %0, %1;" : "=r"(r) : "f"(x));
    return __uint_as_float(r);
}

__device__ __forceinline__ void mma_tf32(float c[4],
                                         uint32_t a0, uint32_t a1, uint32_t a2, uint32_t a3,
                                         uint32_t b0, uint32_t b1) {
    asm volatile(
        "mma.sync.aligned.m16n8k8.row.col.f32.tf32.tf32.f32 "
        "{%0,%1,%2,%3}, {%4,%5,%6,%7}, {%8,%9}, {%0,%1,%2,%3};\n"
        : "+f"(c[0]), "+f"(c[1]), "+f"(c[2]), "+f"(c[3])
        : "r"(a0), "r"(a1), "r"(a2), "r"(a3), "r"(b0), "r"(b1));
}

__device__ __forceinline__ void cp_async16(uint32_t smem_addr, const void* gptr) {
    asm volatile("cp.async.cg.shared.global [%0], [%1], 16;"
                 :: "r"(smem_addr), "l"(gptr));
}

// ---------------------------------------------------------------------------
// Fused QKV projection GEMM (1xTF32, cp.async double-buffered raw staging).
// grid (32, 8, 3): blockIdx.z = 0 -> g_qx (permuted), 1 -> g_kx (permuted),
// 2 -> g_vx (natural) + race-free colsum partials to g_vcsp.
// ---------------------------------------------------------------------------
__global__ __launch_bounds__(256) void qkv_gemm(const float* __restrict__ Aq,
                                                const float* __restrict__ Ak,
                                                const float* __restrict__ Wq,
                                                const float* __restrict__ Wk,
                                                const float* __restrict__ Wv,
                                                const float* __restrict__ bq,
                                                const float* __restrict__ bk,
                                                const float* __restrict__ bv) {
    __shared__ float As[2][128 * 20];
    __shared__ float Bs[2][128 * 20];

    const int mode = blockIdx.z;
    const float* A    = (mode == 0) ? Aq : Ak;
    const float* W    = (mode == 0) ? Wq : (mode == 1) ? Wk : Wv;
    const float* bias = (mode == 0) ? bq : (mode == 1) ? bk : bv;

    const int tid  = threadIdx.x;
    const int lane = tid & 31;
    const int warp = tid >> 5;
    const int wm   = warp & 1;
    const int wn   = warp >> 1;
    const int m0   = blockIdx.x * 128;
    const int n0   = blockIdx.y * 128;

    const int r0 = tid >> 2;
    const int c0 = (tid & 3) * 4;

    float c[4][4][4];
#pragma unroll
    for (int i = 0; i < 4; i++)
#pragma unroll
        for (int j = 0; j < 4; j++)
#pragma unroll
            for (int k = 0; k < 4; k++) c[i][j][k] = 0.f;

    {
        uint32_t as = (uint32_t)__cvta_generic_to_shared(&As[0][0]);
        uint32_t bs = (uint32_t)__cvta_generic_to_shared(&Bs[0][0]);
#pragma unroll
        for (int i = 0; i < 2; i++) {
            int r = r0 + i * 64;
            cp_async16(as + (r * 20 + c0) * 4, A + (size_t)(m0 + r) * 1024 + c0);
            cp_async16(bs + (r * 20 + c0) * 4, W + (size_t)(n0 + r) * 1024 + c0);
        }
        asm volatile("cp.async.commit_group;");
    }

    for (int kt = 0; kt < 64; kt++) {
        asm volatile("cp.async.wait_group 0;");
        __syncthreads();

        if (kt + 1 < 64) {
            int buf = (kt + 1) & 1;
            int k0  = (kt + 1) * 16;
            uint32_t as = (uint32_t)__cvta_generic_to_shared(&As[buf][0]);
            uint32_t bs = (uint32_t)__cvta_generic_to_shared(&Bs[buf][0]);
#pragma unroll
            for (int i = 0; i < 2; i++) {
                int r = r0 + i * 64;
                cp_async16(as + (r * 20 + c0) * 4, A + (size_t)(m0 + r) * 1024 + k0 + c0);
                cp_async16(bs + (r * 20 + c0) * 4, W + (size_t)(n0 + r) * 1024 + k0 + c0);
            }
            asm volatile("cp.async.commit_group;");
        }

        const float* Ab = As[kt & 1];
        const float* Bb = Bs[kt & 1];
#pragma unroll
        for (int kg = 0; kg < 16; kg += 8) {
            uint32_t bh[4][2];
#pragma unroll
            for (int nt = 0; nt < 4; nt++) {
                int boff = (wn * 32 + nt * 8 + (lane >> 2)) * 20 + kg + (lane & 3);
                bh[nt][0] = __float_as_uint(Bb[boff]);
                bh[nt][1] = __float_as_uint(Bb[boff + 4]);
            }
#pragma unroll
            for (int mt = 0; mt < 4; mt++) {
                int aoff = (wm * 64 + mt * 16 + (lane >> 2)) * 20 + kg + (lane & 3);
                uint32_t a0 = __float_as_uint(Ab[aoff]);
                uint32_t a1 = __float_as_uint(Ab[aoff + 8 * 20]);
                uint32_t a2 = __float_as_uint(Ab[aoff + 4]);
                uint32_t a3 = __float_as_uint(Ab[aoff + 8 * 20 + 4]);
#pragma unroll
                for (int nt = 0; nt < 4; nt++)
                    mma_tf32(c[mt][nt], a0, a1, a2, a3, bh[nt][0], bh[nt][1]);
            }
        }
    }

    __syncthreads();

    float csum[4][2];
#pragma unroll
    for (int nt = 0; nt < 4; nt++) { csum[nt][0] = 0.f; csum[nt][1] = 0.f; }

#pragma unroll
    for (int mt = 0; mt < 4; mt++) {
#pragma unroll
        for (int nt = 0; nt < 4; nt++) {
#pragma unroll
            for (int j = 0; j < 4; j++) {
                int row = m0 + wm * 64 + mt * 16 + (lane >> 2) + ((j >> 1) << 3);
                int col = n0 + wn * 32 + nt * 8 + 2 * (lane & 3) + (j & 1);
                float v = c[mt][nt][j] + bias[col];
                int b  = row >> 11;
                int s  = row & 2047;
                int h  = col >> 6;
                int dk = col & 63;
                if (mode == 2) {
                    csum[nt][j & 1] += v;
                    g_vx[(((size_t)(b * H_ + h)) * S_ + s) * DK_ + dk] = v;
                } else {
                    int dkp = (dk & 56) | ((dk & 3) << 1) | ((dk >> 2) & 1);
                    float* dst = (mode == 0) ? g_qx : g_kx;
                    dst[(((size_t)(b * H_ + h)) * S_ + s) * DK_ + dkp] = v;
                }
            }
        }
    }

    if (mode == 2) {
        // reduce colsums across the 8 lanes sharing a column; write race-free
        // partial slot (x&15)*2+wm (each element written by exactly one thread)
        const int slot = (blockIdx.x & 15) * 2 + wm;
        const int b    = m0 >> 11;
#pragma unroll
        for (int nt = 0; nt < 4; nt++) {
#pragma unroll
            for (int p = 0; p < 2; p++) {
                float v = csum[nt][p];
                v += __shfl_down_sync(0xffffffffu, v, 16);
                v += __shfl_down_sync(0xffffffffu, v, 8);
                v += __shfl_down_sync(0xffffffffu, v, 4);
                if (lane < 4) {
                    int col = n0 + wn * 32 + nt * 8 + 2 * lane + p;
                    int bh  = b * H_ + (col >> 6);
                    g_vcsp[slot][bh * 64 + (col & 63)] = v;
                }
            }
        }
    }
}

// ---------------------------------------------------------------------------
// Dense GEMM (3xTF32 RN via register hi/lo split; cp.async raw staging) FUSED
// with the attn normalization stream.
// ---------------------------------------------------------------------------
__global__ __launch_bounds__(256) void dense_gemm(const float* __restrict__ W,
                                                  const float* __restrict__ bias,
                                                  float* __restrict__ attn) {
    __shared__ float As[2][128 * 20];
    __shared__ float Bs[2][128 * 20];

    const float* Ap = g_ctx;

    const int tid  = threadIdx.x;
    const int lane = tid & 31;
    const int warp = tid >> 5;
    const int wm   = warp & 1;
    const int wn   = warp >> 1;
    const int m0   = blockIdx.x * 128;
    const int n0   = blockIdx.y * 128;

    const int r0 = tid >> 2;
    const int c0 = (tid & 3) * 4;

    const int bid = blockIdx.y * 32 + blockIdx.x;
    float4* ap = (float4*)attn;
    const size_t nbase = (size_t)bid * 131072;

    float c[4][4][4];
#pragma unroll
    for (int i = 0; i < 4; i++)
#pragma unroll
        for (int j = 0; j < 4; j++)
#pragma unroll
            for (int k = 0; k < 4; k++) c[i][j][k] = 0.f;

    {
        uint32_t as = (uint32_t)__cvta_generic_to_shared(&As[0][0]);
        uint32_t bs = (uint32_t)__cvta_generic_to_shared(&Bs[0][0]);
#pragma unroll
        for (int i = 0; i < 2; i++) {
            int r = r0 + i * 64;
            cp_async16(as + (r * 20 + c0) * 4, Ap + (size_t)(m0 + r) * 1024 + c0);
            cp_async16(bs + (r * 20 + c0) * 4, W + (size_t)(n0 + r) * 1024 + c0);
        }
        asm volatile("cp.async.commit_group;");
    }

    for (int kt = 0; kt < 64; kt++) {
        asm volatile("cp.async.wait_group 0;");
        __syncthreads();

        if (kt + 1 < 64) {
            int buf = (kt + 1) & 1;
            int k0  = (kt + 1) * 16;
            uint32_t as = (uint32_t)__cvta_generic_to_shared(&As[buf][0]);
            uint32_t bs = (uint32_t)__cvta_generic_to_shared(&Bs[buf][0]);
#pragma unroll
            for (int i = 0; i < 2; i++) {
                int r = r0 + i * 64;
                cp_async16(as + (r * 20 + c0) * 4, Ap + (size_t)(m0 + r) * 1024 + k0 + c0);
                cp_async16(bs + (r * 20 + c0) * 4, W + (size_t)(n0 + r) * 1024 + k0 + c0);
            }
            asm volatile("cp.async.commit_group;");
        }

        // attn normalization chunk (2048 float4, coalesced)
        {
            size_t base = nbase + (size_t)kt * 2048 + tid;
#pragma unroll
            for (int i = 0; i < 8; i++) {
                size_t idx = base + (size_t)i * 256;
                float inv = g_rinv[idx >> 9];
                float4 v = ap[idx];
                v.x *= inv; v.y *= inv; v.z *= inv; v.w *= inv;
                ap[idx] = v;
            }
        }

        const float* Ab = As[kt & 1];
        const float* Bb = Bs[kt & 1];
#pragma unroll
        for (int kg = 0; kg < 16; kg += 8) {
            uint32_t bh[4][2], bl[4][2];
#pragma unroll
            for (int nt = 0; nt < 4; nt++) {
                int boff = (wn * 32 + nt * 8 + (lane >> 2)) * 20 + kg + (lane & 3);
                float rb0 = Bb[boff];
                float rb1 = Bb[boff + 4];
                float hb0 = tf32_hi(rb0);
                float hb1 = tf32_hi(rb1);
                bh[nt][0] = __float_as_uint(hb0);
                bh[nt][1] = __float_as_uint(hb1);
                bl[nt][0] = __float_as_uint(rb0 - hb0);
                bl[nt][1] = __float_as_uint(rb1 - hb1);
            }
#pragma unroll
            for (int mt = 0; mt < 4; mt++) {
                int aoff = (wm * 64 + mt * 16 + (lane >> 2)) * 20 + kg + (lane & 3);
                float ra0 = Ab[aoff];
                float ra1 = Ab[aoff + 8 * 20];
                float ra2 = Ab[aoff + 4];
                float ra3 = Ab[aoff + 8 * 20 + 4];
                float ha0 = tf32_hi(ra0), ha1 = tf32_hi(ra1);
                float ha2 = tf32_hi(ra2), ha3 = tf32_hi(ra3);
                uint32_t ah0 = __float_as_uint(ha0), ah1 = __float_as_uint(ha1);
                uint32_t ah2 = __float_as_uint(ha2), ah3 = __float_as_uint(ha3);
                uint32_t al0 = __float_as_uint(ra0 - ha0), al1 = __float_as_uint(ra1 - ha1);
                uint32_t al2 = __float_as_uint(ra2 - ha2), al3 = __float_as_uint(ra3 - ha3);
#pragma unroll
                for (int nt = 0; nt < 4; nt++) {
                    mma_tf32(c[mt][nt], ah0, ah1, ah2, ah3, bh[nt][0], bh[nt][1]);
                    mma_tf32(c[mt][nt], ah0, ah1, ah2, ah3, bl[nt][0], bl[nt][1]);
                    mma_tf32(c[mt][nt], al0, al1, al2, al3, bh[nt][0], bh[nt][1]);
                }
            }
        }
    }

    __syncthreads();
#pragma unroll
    for (int mt = 0; mt < 4; mt++) {
#pragma unroll
        for (int nt = 0; nt < 4; nt++) {
#pragma unroll
            for (int j = 0; j < 4; j++) {
                int row = m0 + wm * 64 + mt * 16 + (lane >> 2) + ((j >> 1) << 3);
                int col = n0 + wn * 32 + nt * 8 + 2 * (lane & 3) + (j & 1);
                float v = c[mt][nt][j] + bias[col];
                g_dense[(size_t)row * 1024 + col] = v > 0.f ? v : 0.f;
            }
        }
    }
}

// ---------------------------------------------------------------------------
// Fused attention kernel (v7: 32 q-rows/warp, 128 q-rows/block, 3-stage
// cp.async pipeline; PV transposed with shuffle-fed dp).
// grid = (S/128, H*B), block = 256. 1 CTA/SM.
// ---------------------------------------------------------------------------
#define KSTR 72
#define VSTR 72
#define KVBUF (64 * KSTR + 64 * VSTR)   // 9216 floats per buffer
#define NSTAGE 3
#define OSTR 66
#define ATTN_SMEM_FLOATS (NSTAGE * KVBUF + 128 + 64)   // + rowsum + vc

__global__ __launch_bounds__(256, 1) void attn_kernel(float* __restrict__ attn_out) {
    extern __shared__ float smf[];
    float* rs   = smf + NSTAGE * KVBUF;      // rowsum[128]
    float* vcs  = rs + 128;                  // V colsum[64]
    float* Obuf = smf;                       // epilogue alias: 2 x 128 x 66

    const int tid  = threadIdx.x;
    const int lane = tid & 31;
    const int warp = tid >> 5;
    const int wm   = warp & 3;               // q-row group (32 rows each)
    const int wn   = warp >> 2;              // kv half
    const int g    = lane >> 2;
    const int j    = lane & 3;
    const int hb   = blockIdx.y;             // h*B + b
    const int h    = hb >> 1;
    const int b    = hb & 1;
    const int q0   = blockIdx.x * 128;

    const float* qbase = g_qx + ((size_t)(b * H_ + h)) * S_ * DK_;
    const float* kbase = g_kx + ((size_t)(b * H_ + h)) * S_ * DK_;
    const float* vbase = g_vx + ((size_t)(b * H_ + h)) * S_ * DK_;
    const float invT = 0.03125f;             // 1/sqrt(1024)

    if (tid < 128) rs[tid] = 0.f;

    const int sr  = tid >> 4;                // base row 0..15 (+16 per i)
    const int sc4 = (tid & 15) * 4;          // col 0..60

    // prologue: issue tiles 0 and 1 (two commit groups)
#pragma unroll
    for (int t = 0; t < 2; t++) {
        float* Kb = smf + t * KVBUF;
        float* Vb = Kb + 64 * KSTR;
        uint32_t ksm = (uint32_t)__cvta_generic_to_shared(Kb);
        uint32_t vsm = (uint32_t)__cvta_generic_to_shared(Vb);
        const float* kb = kbase + (size_t)t * 64 * 64;
        const float* vb = vbase + (size_t)t * 64 * 64;
#pragma unroll
        for (int i = 0; i < 4; i++) {
            int r = sr + i * 16;
            cp_async16(ksm + (r * KSTR + sc4) * 4, kb + (size_t)r * 64 + sc4);
            cp_async16(vsm + (r * VSTR + sc4) * 4, vb + (size_t)r * 64 + sc4);
        }
        asm volatile("cp.async.commit_group;");
    }

    // Q fragments in registers (RN tf32, pre-scaled), permuted layout
    uint32_t qa[2][8][4];
#pragma unroll
    for (int mq = 0; mq < 2; mq++) {
        const float* qr0 = qbase + (size_t)(q0 + wm * 32 + mq * 16 + g) * 64;
        const float* qr1 = qr0 + 8 * 64;
#pragma unroll
        for (int kg = 0; kg < 8; kg++) {
            float2 u0 = *(const float2*)(qr0 + kg * 8 + 2 * j);
            float2 u1 = *(const float2*)(qr1 + kg * 8 + 2 * j);
            qa[mq][kg][0] = __float_as_uint(tf32_hi(u0.x * invT));
            qa[mq][kg][2] = __float_as_uint(tf32_hi(u0.y * invT));
            qa[mq][kg][1] = __float_as_uint(tf32_hi(u1.x * invT));
            qa[mq][kg][3] = __float_as_uint(tf32_hi(u1.y * invT));
        }
    }

    float o[4][2][2][4];
#pragma unroll
    for (int mt = 0; mt < 4; mt++)
#pragma unroll
        for (int mq = 0; mq < 2; mq++)
#pragma unroll
            for (int nq = 0; nq < 2; nq++)
#pragma unroll
                for (int k = 0; k < 4; k++) o[mt][mq][nq][k] = 0.f;
    float rsv[2][2] = {{0.f, 0.f}, {0.f, 0.f}};

    const int src0 = 4 * g + (j >> 1);
    const int src1 = src0 + 2;
    const bool jodd = (j & 1) != 0;

    int buf = 0;
    for (int kt = 0; kt < 32; kt++) {
        float* Kb = smf + buf * KVBUF;
        float* Vb = Kb + 64 * KSTR;

        if (kt < 30) {
            asm volatile("cp.async.wait_group 1;");
        } else {
            asm volatile("cp.async.wait_group 0;");
        }
        __syncthreads();

        if (kt + 2 < 32) {
            int nbuf = buf + 2;
            if (nbuf >= NSTAGE) nbuf -= NSTAGE;
            float* Kn = smf + nbuf * KVBUF;
            float* Vn = Kn + 64 * KSTR;
            uint32_t ksm = (uint32_t)__cvta_generic_to_shared(Kn);
            uint32_t vsm = (uint32_t)__cvta_generic_to_shared(Vn);
            const float* kb = kbase + (size_t)(kt + 2) * 64 * 64;
            const float* vb = vbase + (size_t)(kt + 2) * 64 * 64;
#pragma unroll
            for (int i = 0; i < 4; i++) {
                int r = sr + i * 16;
                cp_async16(ksm + (r * KSTR + sc4) * 4, kb + (size_t)r * 64 + sc4);
                cp_async16(vsm + (r * VSTR + sc4) * 4, vb + (size_t)r * 64 + sc4);
            }
            asm volatile("cp.async.commit_group;");
        }

        // scores
        float s[2][4][4];
#pragma unroll
        for (int mq = 0; mq < 2; mq++)
#pragma unroll
            for (int i = 0; i < 4; i++)
#pragma unroll
                for (int k = 0; k < 4; k++) s[mq][i][k] = 0.f;
#pragma unroll
        for (int kg = 0; kg < 8; kg++) {
            float2 kb2[4];
#pragma unroll
            for (int nt = 0; nt < 4; nt++)
                kb2[nt] = *(const float2*)(Kb + (wn * 32 + nt * 8 + g) * KSTR + kg * 8 + 2 * j);
#pragma unroll
            for (int mq = 0; mq < 2; mq++)
#pragma unroll
                for (int nt = 0; nt < 4; nt++)
                    mma_tf32(s[mq][nt], qa[mq][kg][0], qa[mq][kg][1],
                             qa[mq][kg][2], qa[mq][kg][3],
                             __float_as_uint(kb2[nt].x), __float_as_uint(kb2[nt].y));
        }

        // exp -> gmem attn (unnormalized), rowsum regs; dp overwrites s
        const int k0 = kt * 64;
#pragma unroll
        for (int mq = 0; mq < 2; mq++) {
            float* ab = attn_out +
                ((size_t)hb * S_ + q0 + wm * 32 + mq * 16 + g) * S_ + k0 + wn * 32;
#pragma unroll
            for (int nt = 0; nt < 4; nt++) {
                float p0 = __expf(s[mq][nt][0]);
                float p1 = __expf(s[mq][nt][1]);
                float p2 = __expf(s[mq][nt][2]);
                float p3 = __expf(s[mq][nt][3]);
                rsv[mq][0] += p0 + p1;
                rsv[mq][1] += p2 + p3;
                *(float2*)(ab + nt * 8 + 2 * j) = make_float2(p0, p1);
                *(float2*)(ab + (size_t)8 * S_ + nt * 8 + 2 * j) = make_float2(p2, p3);
                s[mq][nt][0] = p0 - 1.f;
                s[mq][nt][1] = p1 - 1.f;
                s[mq][nt][2] = p2 - 1.f;
                s[mq][nt][3] = p3 - 1.f;
            }
        }

        // PV (transposed)
#pragma unroll
        for (int kp = 0; kp < 4; kp++) {
            uint32_t av[4][4];
#pragma unroll
            for (int mt = 0; mt < 4; mt++) {
                int aoff = (wn * 32 + kp * 8 + j) * VSTR + mt * 16 + g;
                av[mt][0] = __float_as_uint(Vb[aoff]);
                av[mt][1] = __float_as_uint(Vb[aoff + 8]);
                av[mt][2] = __float_as_uint(Vb[aoff + 4 * VSTR]);
                av[mt][3] = __float_as_uint(Vb[aoff + 4 * VSTR + 8]);
            }
#pragma unroll
            for (int mq = 0; mq < 2; mq++) {
#pragma unroll
                for (int nq = 0; nq < 2; nq++) {
                    float v00 = __shfl_sync(0xffffffffu, s[mq][kp][2 * nq + 0], src0);
                    float v01 = __shfl_sync(0xffffffffu, s[mq][kp][2 * nq + 1], src0);
                    float v10 = __shfl_sync(0xffffffffu, s[mq][kp][2 * nq + 0], src1);
                    float v11 = __shfl_sync(0xffffffffu, s[mq][kp][2 * nq + 1], src1);
                    uint32_t b0 = __float_as_uint(jodd ? v01 : v00);
                    uint32_t b1 = __float_as_uint(jodd ? v11 : v10);
#pragma unroll
                    for (int mt = 0; mt < 4; mt++)
                        mma_tf32(o[mt][mq][nq], av[mt][0], av[mt][1], av[mt][2], av[mt][3],
                                 b0, b1);
                }
            }
        }

        buf++;
        if (buf == NSTAGE) buf = 0;
    }

    // --- epilogue ---
    __syncthreads();   // all PV reads of the KV buffers complete before aliasing
    {
        float* Ob = Obuf + wn * 128 * OSTR;
#pragma unroll
        for (int mt = 0; mt < 4; mt++) {
#pragma unroll
            for (int mq = 0; mq < 2; mq++) {
#pragma unroll
                for (int nq = 0; nq < 2; nq++) {
                    int qb = wm * 32 + mq * 16 + nq * 8 + 2 * j;
                    int nb = mt * 16 + g;
                    Ob[qb * OSTR + nb]           = o[mt][mq][nq][0];
                    Ob[(qb + 1) * OSTR + nb]     = o[mt][mq][nq][1];
                    Ob[qb * OSTR + nb + 8]       = o[mt][mq][nq][2];
                    Ob[(qb + 1) * OSTR + nb + 8] = o[mt][mq][nq][3];
                }
            }
        }
    }
#pragma unroll
    for (int mq = 0; mq < 2; mq++) {
        float r0 = rsv[mq][0], r1 = rsv[mq][1];
        r0 += __shfl_xor_sync(0xffffffffu, r0, 1);
        r0 += __shfl_xor_sync(0xffffffffu, r0, 2);
        r1 += __shfl_xor_sync(0xffffffffu, r1, 1);
        r1 += __shfl_xor_sync(0xffffffffu, r1, 2);
        if (j == 0) {
            atomicAdd(&rs[wm * 32 + mq * 16 + g], r0);
            atomicAdd(&rs[wm * 32 + mq * 16 + 8 + g], r1);
        }
    }
    __syncthreads();
    if (tid < 128) {
        float inv = 1.0f / rs[tid];
        g_rinv[(size_t)hb * S_ + q0 + tid] = inv;
        rs[tid] = inv;
    } else if (tid < 192) {
        // V colsum from the 32 race-free partials
        int d = tid - 128;
        float svc = 0.f;
#pragma unroll
        for (int p = 0; p < 32; p++)
            svc += g_vcsp[p][(b * H_ + h) * 64 + d];
        vcs[d] = svc;
    }
    __syncthreads();

#pragma unroll
    for (int i = 0; i < 32; i++) {
        int lin = tid + i * 256;
        int qr  = lin >> 6;
        int d   = lin & 63;
        float val = (Obuf[qr * OSTR + d] + Obuf[128 * OSTR + qr * OSTR + d] + vcs[d]) * rs[qr];
        g_ctx[((size_t)(b * S_ + q0 + qr)) * D_ + h * 64 + d] = val;
    }
}

// ---------------------------------------------------------------------------
// LayerNorm over rows of g_dense -> out
// ---------------------------------------------------------------------------
__global__ __launch_bounds__(256) void ln_kernel(const float* __restrict__ lg,
                                                 const float* __restrict__ lb,
                                                 float* __restrict__ out) {
    const int row = blockIdx.x;
    const int tid = threadIdx.x;
    const float* x = g_dense + (size_t)row * 1024;
    float4 xv = *(const float4*)(x + tid * 4);
    float s  = xv.x + xv.y + xv.z + xv.w;
    float ss = fmaf(xv.x, xv.x, fmaf(xv.y, xv.y, fmaf(xv.z, xv.z, xv.w * xv.w)));
#pragma unroll
    for (int off = 16; off > 0; off >>= 1) {
        s  += __shfl_xor_sync(0xffffffffu, s, off);
        ss += __shfl_xor_sync(0xffffffffu, ss, off);
    }
    __shared__ float sm1[8], sm2[8];
    if ((tid & 31) == 0) { sm1[tid >> 5] = s; sm2[tid >> 5] = ss; }
    __syncthreads();
    if (tid < 32) {
        float a  = (tid < 8) ? sm1[tid] : 0.f;
        float b2 = (tid < 8) ? sm2[tid] : 0.f;
#pragma unroll
        for (int off = 4; off > 0; off >>= 1) {
            a  += __shfl_xor_sync(0xffffffffu, a, off);
            b2 += __shfl_xor_sync(0xffffffffu, b2, off);
        }
        if (tid == 0) { sm1[0] = a; sm2[0] = b2; }
    }
    __syncthreads();
    float mean = sm1[0] * (1.0f / 1024.0f);
    float var  = sm2[0] * (1.0f / 1024.0f) - mean * mean;
    float rstd = rsqrtf(var + 1e-5f);
    float4 gv = *(const float4*)(lg + tid * 4);
    float4 bv = *(const float4*)(lb + tid * 4);
    float4 ov;
    ov.x = (xv.x - mean) * rstd * gv.x + bv.x;
    ov.y = (xv.y - mean) * rstd * gv.y + bv.y;
    ov.z = (xv.z - mean) * rstd * gv.z + bv.z;
    ov.w = (xv.w - mean) * rstd * gv.w + bv.w;
    *(float4*)(out + (size_t)row * 1024 + tid * 4) = ov;
}

// ---------------------------------------------------------------------------
// Launch (4 launches: fused qkv, attn, fused dense+norm, ln)
// ---------------------------------------------------------------------------
extern "C" void kernel_launch(void* const* d_in, const int* in_sizes, int n_in,
                              void* d_out, int out_size) {
    const float* k_in = (const float*)d_in[0];
    const float* q_in = (const float*)d_in[1];
    const float* wk   = (const float*)d_in[2];
    const float* bk   = (const float*)d_in[3];
    const float* wq   = (const float*)d_in[4];
    const float* bq   = (const float*)d_in[5];
    const float* wv   = (const float*)d_in[6];
    const float* bv   = (const float*)d_in[7];
    const float* wd   = (const float*)d_in[8];
    const float* bd   = (const float*)d_in[9];
    const float* lg   = (const float*)d_in[10];
    const float* lb   = (const float*)d_in[11];

    float* out  = (float*)d_out;
    float* attn = out + (size_t)B_ * S_ * D_;  // tuple order: (out, attn)

    const int attn_smem_bytes = ATTN_SMEM_FLOATS * 4;
    cudaFuncSetAttribute(attn_kernel, cudaFuncAttributeMaxDynamicSharedMemorySize,
                         attn_smem_bytes);

    qkv_gemm<<<dim3(MTOT / 128, D_ / 128, 3), 256>>>(q_in, k_in, wq, wk, wv,
                                                     bq, bk, bv);

    attn_kernel<<<dim3(S_ / 128, HB_), 256, attn_smem_bytes>>>(attn);

    dense_gemm<<<dim3(MTOT / 128, D_ / 128), 256>>>(wd, bd, attn);

    ln_kernel<<<MTOT, 256>>>(lg, lb, out);
}